// round 12
// baseline (speedup 1.0000x reference)
#include <cuda_runtime.h>
#include <cuda_bf16.h>
#include <cuda_fp16.h>

#define N_TOK 8192
#define DMODEL 1024
#define DFF 4096
#define NEXP 8
#define NPAIR (N_TOK * 2)
#define EPSF 1.1920928955078125e-07f
#define STAGE_BF 65536u
#define SMEM_BF (3 * 65536)
#define STAGE_HF 49152u
#define SMEM_HF (3 * 49152)
typedef __nv_bfloat16 bf;
typedef __nv_bfloat162 bf2;
typedef long long ll;

__device__ float g_h[(size_t)N_TOK * DMODEL];
__device__ float g_Oe[(size_t)NPAIR * DMODEL];
__device__ bf g_sH[(size_t)N_TOK*DMODEL], g_sL[(size_t)N_TOK*DMODEL];
__device__ bf g_WinH[(size_t)DMODEL*DMODEL], g_WinL[(size_t)DMODEL*DMODEL];
__device__ __half g_hHf[(size_t)N_TOK*DMODEL];
__device__ __half g_yHf[(size_t)N_TOK*DMODEL];
__device__ __half g_THf[(size_t)NPAIR*DFF];
__device__ __half g_WgF[(size_t)NEXP*DFF*DMODEL];
__device__ __half g_WuF[(size_t)NEXP*DFF*DMODEL];
__device__ __half g_WdF[(size_t)NEXP*DMODEL*DFF];
__device__ __half g_WoF[(size_t)DMODEL*DMODEL];
__device__ int g_cnt[NEXP], g_off[NEXP+1], g_cur[NEXP];
__device__ int g_pairtok[NPAIR], g_slotof[NPAIR], g_topidx[NPAIR];
__device__ float g_topgate[NPAIR];

__device__ __forceinline__ unsigned su32(const void* p){
    unsigned a; asm("{ .reg .u64 t; cvta.to.shared.u64 t, %1; cvt.u32.u64 %0, t; }":"=r"(a):"l"(p)); return a;
}
__device__ __forceinline__ void cp16(unsigned d, const void* s){
    asm volatile("cp.async.cg.shared.global [%0], [%1], 16;"::"r"(d),"l"(s));
}
__device__ __forceinline__ unsigned swz(unsigned off){ return off ^ ((off>>3)&0x70u); }
__device__ __forceinline__ void ldsm4(unsigned* r, unsigned a){
    asm volatile("ldmatrix.sync.aligned.m8n8.x4.shared.b16 {%0,%1,%2,%3}, [%4];"
        :"=r"(r[0]),"=r"(r[1]),"=r"(r[2]),"=r"(r[3]):"r"(a));
}
__device__ __forceinline__ void mma_bf(float* c, const unsigned* a, unsigned b0, unsigned b1){
    asm volatile("mma.sync.aligned.m16n8k16.row.col.f32.bf16.bf16.f32 "
        "{%0,%1,%2,%3},{%4,%5,%6,%7},{%8,%9},{%0,%1,%2,%3};"
        :"+f"(c[0]),"+f"(c[1]),"+f"(c[2]),"+f"(c[3])
        :"r"(a[0]),"r"(a[1]),"r"(a[2]),"r"(a[3]),"r"(b0),"r"(b1));
}
__device__ __forceinline__ void mma_hf(float* c, const unsigned* a, unsigned b0, unsigned b1){
    asm volatile("mma.sync.aligned.m16n8k16.row.col.f32.f16.f16.f32 "
        "{%0,%1,%2,%3},{%4,%5,%6,%7},{%8,%9},{%0,%1,%2,%3};"
        :"+f"(c[0]),"+f"(c[1]),"+f"(c[2]),"+f"(c[3])
        :"r"(a[0]),"r"(a[1]),"r"(a[2]),"r"(a[3]),"r"(b0),"r"(b1));
}
__device__ __forceinline__ void split2(float x, bf& h, bf& l){
    h = __float2bfloat16(x); l = __float2bfloat16(x - __bfloat162float(h));
}

__global__ void init_counts(){ if (threadIdx.x < NEXP) g_cnt[threadIdx.x] = 0; }
__global__ void scan_offsets(){
    if (threadIdx.x == 0){ int s=0; for(int e=0;e<NEXP;e++){ g_off[e]=s; s+=g_cnt[e]; } g_off[NEXP]=s; }
    if (threadIdx.x < NEXP) g_cur[threadIdx.x] = 0;
}
__global__ void scatter_pairs(){
    int t = blockIdx.x*blockDim.x + threadIdx.x; if (t >= N_TOK) return;
    for (int k=0;k<2;k++){
        int e = g_topidx[2*t+k];
        int slot = g_off[e] + atomicAdd(&g_cur[e],1);
        g_pairtok[slot] = t; g_slotof[2*t+k] = slot;
    }
}
__global__ void convert_hilo(const float* __restrict__ x, bf* __restrict__ h, bf* __restrict__ l, int n4){
    int i = blockIdx.x*blockDim.x + threadIdx.x; if (i >= n4) return;
    float4 v = ((const float4*)x)[i];
    bf2 p0,p1,q0,q1;
    split2(v.x,p0.x,q0.x); split2(v.y,p0.y,q0.y); split2(v.z,p1.x,q1.x); split2(v.w,p1.y,q1.y);
    ((bf2*)h)[2*i]=p0; ((bf2*)h)[2*i+1]=p1; ((bf2*)l)[2*i]=q0; ((bf2*)l)[2*i+1]=q1;
}
__global__ void convert_f16(const float* __restrict__ x, __half* __restrict__ o, int n4){
    int i = blockIdx.x*blockDim.x + threadIdx.x; if (i >= n4) return;
    float4 v = ((const float4*)x)[i];
    __half2 p0, p1;
    p0.x = __float2half_rn(v.x); p0.y = __float2half_rn(v.y);
    p1.x = __float2half_rn(v.z); p1.y = __float2half_rn(v.w);
    ((__half2*)o)[2*i]=p0; ((__half2*)o)[2*i+1]=p1;
}
__global__ void rmsnorm_f16(const float* __restrict__ X, const float* __restrict__ w,
                            float* __restrict__ Y, __half* __restrict__ YH){
    int row = blockIdx.x, tid = threadIdx.x;
    float4 v = ((const float4*)(X + (ll)row*DMODEL))[tid];
    float ss = v.x*v.x+v.y*v.y+v.z*v.z+v.w*v.w;
    __shared__ float red[8];
    for (int o=16;o;o>>=1) ss += __shfl_xor_sync(~0u, ss, o);
    if ((tid&31)==0) red[tid>>5]=ss;
    __syncthreads();
    float tot = red[0]+red[1]+red[2]+red[3]+red[4]+red[5]+red[6]+red[7];
    float r = rsqrtf(tot*(1.0f/DMODEL)+EPSF);
    float4 wv = ((const float4*)w)[tid];
    float4 o4 = make_float4(v.x*r*wv.x, v.y*r*wv.y, v.z*r*wv.z, v.w*r*wv.w);
    ((float4*)(Y + (ll)row*DMODEL))[tid] = o4;
    __half2 p0,p1;
    p0.x = __float2half_rn(o4.x); p0.y = __float2half_rn(o4.y);
    p1.x = __float2half_rn(o4.z); p1.y = __float2half_rn(o4.w);
    __half2* ph=(__half2*)(YH+(ll)row*DMODEL);
    ph[2*tid]=p0; ph[2*tid+1]=p1;
}
__global__ void router_kernel(const float* __restrict__ h, const float* __restrict__ Wr, const float* __restrict__ bias){
    int warp = (blockIdx.x*blockDim.x+threadIdx.x)>>5, lane = threadIdx.x&31;
    if (warp >= N_TOK) return;
    const float* hr = h + (ll)warp*DMODEL;
    float acc[NEXP];
    #pragma unroll
    for (int e=0;e<NEXP;e++) acc[e]=0.f;
    for (int d=lane; d<DMODEL; d+=32){
        float hv = hr[d];
        #pragma unroll
        for (int e=0;e<NEXP;e++) acc[e] += hv*Wr[e*DMODEL+d];
    }
    #pragma unroll
    for (int e=0;e<NEXP;e++)
        for (int o=16;o;o>>=1) acc[e] += __shfl_xor_sync(~0u, acc[e], o);
    if (lane==0){
        float b0=-1e30f,b1=-1e30f; int i0=0,i1=0;
        #pragma unroll
        for (int e=0;e<NEXP;e++){
            float v = acc[e]+bias[e];
            if (v>b0){ b1=b0;i1=i0;b0=v;i0=e; } else if (v>b1){ b1=v;i1=e; }
        }
        float m=fmaxf(acc[i0],acc[i1]);
        float e0=expf(acc[i0]-m), e1=expf(acc[i1]-m), inv=1.f/(e0+e1);
        g_topidx[2*warp]=i0; g_topidx[2*warp+1]=i1;
        g_topgate[2*warp]=e0*inv; g_topgate[2*warp+1]=e1*inv;
        atomicAdd(&g_cnt[i0],1); atomicAdd(&g_cnt[i1],1);
    }
}

// ---------- bf16 3-pass dense GEMM (in-proj; protects router), 3-stage pipeline ----------
__global__ __launch_bounds__(256) void mm_bf(
    const bf* __restrict__ Ah, const bf* __restrict__ Al,
    const bf* __restrict__ B0h, const bf* __restrict__ B0l,
    float* __restrict__ C, int Mdense, int K, int Ncols)
{
    extern __shared__ char dsm[];
    int Mloc = Mdense;
    int bm = blockIdx.x*128; if (bm >= Mloc) return;
    int bn = blockIdx.y*128;
    unsigned sb = su32(dsm);
    int tid = threadIdx.x;
    int aslot = tid&7, arow0 = tid>>3;
    int w = tid>>5, lane = tid&31;
    int wm = (w>>2)*64, wn = (w&3)*32;
    float acc[4][4][4];
    #pragma unroll
    for (int i=0;i<4;i++)
        #pragma unroll
        for (int j=0;j<4;j++)
            #pragma unroll
            for (int q=0;q<4;q++) acc[i][j][q] = 0.f;

    int total = K>>6;
    auto load = [&](int kt){
        unsigned base = sb + (unsigned)(kt%3)*STAGE_BF;
        int ke = kt*64 + aslot*8;
        #pragma unroll
        for (int j=0;j<4;j++){
            int r = arow0 + 32*j;
            unsigned sw = swz((unsigned)(r*128 + aslot*16));
            int ar = bm + r;
            cp16(base+sw,        Ah + (ll)ar*K + ke);
            cp16(base+16384u+sw, Al + (ll)ar*K + ke);
            int br = bn + r;
            cp16(base+32768u+sw, B0h + (ll)br*K + ke);
            cp16(base+49152u+sw, B0l + (ll)br*K + ke);
        }
        asm volatile("cp.async.commit_group;":::"memory");
    };
    if (0 < total) load(0);
    if (1 < total) load(1);
    for (int c = 0; c < total; ++c){
        if (c+2 < total) load(c+2);
        if (c+2 < total)      asm volatile("cp.async.wait_group 2;":::"memory");
        else if (c+1 < total) asm volatile("cp.async.wait_group 1;":::"memory");
        else                  asm volatile("cp.async.wait_group 0;":::"memory");
        __syncthreads();

        unsigned base = sb + (unsigned)(c%3)*STAGE_BF;
        int lrow8 = ((lane>>3)&1)*8 + (lane&7);
        #pragma unroll
        for (int ks=0; ks<4; ks++){
            int kb = ks*32 + (lane>>4)*16;
            unsigned BH[2][4], BL[2][4];
            #pragma unroll
            for (int t=0;t<2;t++){
                unsigned sw = swz((unsigned)((wn + t*16 + lrow8)*128 + kb));
                ldsm4(BH[t], base + 32768u + sw);
                ldsm4(BL[t], base + 49152u + sw);
            }
            #pragma unroll
            for (int tm=0;tm<4;tm++){
                unsigned ah[4], al[4];
                unsigned asw = swz((unsigned)((wm + tm*16 + lrow8)*128 + kb));
                ldsm4(ah, base + asw);
                ldsm4(al, base + 16384u + asw);
                #pragma unroll
                for (int t=0;t<2;t++){
                    int j0=2*t, j1=2*t+1;
                    mma_bf(acc[tm][j0], ah, BH[t][0], BH[t][2]);
                    mma_bf(acc[tm][j0], ah, BL[t][0], BL[t][2]);
                    mma_bf(acc[tm][j0], al, BH[t][0], BH[t][2]);
                    mma_bf(acc[tm][j1], ah, BH[t][1], BH[t][3]);
                    mma_bf(acc[tm][j1], ah, BL[t][1], BL[t][3]);
                    mma_bf(acc[tm][j1], al, BH[t][1], BH[t][3]);
                }
            }
        }
        __syncthreads();
    }
    #pragma unroll
    for (int tm=0;tm<4;tm++){
        int r = bm + wm + tm*16 + (lane>>2);
        #pragma unroll
        for (int j=0;j<4;j++){
            float* cc = acc[tm][j];
            int col = bn + wn + j*8 + (lane&3)*2;
            *(float2*)(C + (ll)r*Ncols + col) = make_float2(cc[0],cc[1]);
            *(float2*)(C + (ll)(r+8)*Ncols + col) = make_float2(cc[2],cc[3]);
        }
    }
}

// ---------- fp16 1-pass GEMM, 512 thr, 48KB stages (LTS-friendly), 3-stage ----------
// DUAL=1 (gateup): CTA 256x(64g+64u), warp 32x(32g+32u); epilogue silu(g)*u -> fp16.
// DUAL=0        : CTA 128x256, warp 64x32; fp32 C out.
template<int DUAL, int GROUPED>
__global__ __launch_bounds__(512, 1) void mm_f16(
    const __half* __restrict__ Ah,
    const __half* __restrict__ B0, const __half* __restrict__ B1,
    float* __restrict__ C, __half* __restrict__ TH,
    int Mdense, int K, int Ncols,
    const int* __restrict__ d_off, const int* __restrict__ pairtok, ll strideB)
{
    extern __shared__ char dsm[];
    constexpr int BM = DUAL ? 256 : 128;
    constexpr unsigned ASZ = DUAL ? 32768u : 16384u;   // A rows*128B
    constexpr int AJ = DUAL ? 4 : 2;                    // A 64-row groups
    constexpr int BJ = DUAL ? 2 : 4;                    // B 64-row groups
    int rowBase = 0, Mloc = Mdense, bm;
    const __half *b0 = B0, *b1 = B1;
    if (GROUPED){
        int idx = blockIdx.x, e = 0;
        int base0 = 0, m = 0;
        #pragma unroll 1
        for (; e < NEXP; e++){
            base0 = d_off[e]; m = d_off[e+1]-base0;
            int nt = (m + BM - 1)/BM;
            if (idx < nt) break;
            idx -= nt;
        }
        if (e == NEXP) return;
        rowBase = base0; Mloc = m; bm = idx*BM;
        b0 += (ll)e*strideB;
        if (DUAL) b1 += (ll)e*strideB;
    } else {
        bm = blockIdx.x*BM;
        if (bm >= Mloc) return;
    }
    int bn = blockIdx.y*(DUAL?64:256);

    unsigned sb = su32(dsm);
    int tid = threadIdx.x;
    int aslot = tid&7, arow0 = tid>>3;   // arow0: 0..63
    int ga[AJ];
    #pragma unroll
    for (int j=0;j<AJ;j++){
        int lr = bm + arow0 + 64*j; if (lr > Mloc-1) lr = Mloc-1;
        ga[j] = (GROUPED && DUAL) ? pairtok[rowBase+lr] : (rowBase+lr);
    }
    int w = tid>>5, lane = tid&31;
    int wm = DUAL ? (w>>1)*32 : (w>>3)*64;
    int wn = DUAL ? (w&1)*32  : (w&7)*32;
    constexpr int MT = DUAL ? 2 : 4;
    constexpr int NB = DUAL ? 4 : 2;

    float acc[4][4][4];   // dual: [0..1]=gate, [2..3]=up
    #pragma unroll
    for (int i=0;i<4;i++)
        #pragma unroll
        for (int j=0;j<4;j++)
            #pragma unroll
            for (int q=0;q<4;q++) acc[i][j][q] = 0.f;

    int total = K>>6;
    auto load = [&](int kt){
        unsigned base = sb + (unsigned)(kt%3)*STAGE_HF;
        int ke = kt*64 + aslot*8;
        #pragma unroll
        for (int j=0;j<AJ;j++){
            int r = arow0 + 64*j;
            unsigned sw = swz((unsigned)(r*128 + aslot*16));
            cp16(base+sw, Ah + (ll)ga[j]*K + ke);
        }
        #pragma unroll
        for (int j=0;j<BJ;j++){
            int r = arow0 + 64*j;
            unsigned sw = swz((unsigned)(r*128 + aslot*16));
            const __half* bp; int br;
            if (DUAL && r >= 64){ bp = b1; br = bn + r - 64; }
            else                { bp = b0; br = bn + r; }
            cp16(base+ASZ+sw, bp + (ll)br*K + ke);
        }
        asm volatile("cp.async.commit_group;":::"memory");
    };
    if (0 < total) load(0);
    if (1 < total) load(1);
    for (int c = 0; c < total; ++c){
        if (c+2 < total) load(c+2);
        if (c+2 < total)      asm volatile("cp.async.wait_group 2;":::"memory");
        else if (c+1 < total) asm volatile("cp.async.wait_group 1;":::"memory");
        else                  asm volatile("cp.async.wait_group 0;":::"memory");
        __syncthreads();

        unsigned base = sb + (unsigned)(c%3)*STAGE_HF;
        int lrow8 = ((lane>>3)&1)*8 + (lane&7);
        #pragma unroll
        for (int ks=0; ks<4; ks++){
            int kb = ks*32 + (lane>>4)*16;
            unsigned BH[NB][4];
            #pragma unroll
            for (int t=0;t<NB;t++){
                int nb = (DUAL && t>=2) ? (64 + wn + (t-2)*16) : (wn + t*16);
                ldsm4(BH[t], base + ASZ + swz((unsigned)((nb + lrow8)*128 + kb)));
            }
            #pragma unroll
            for (int tm=0;tm<MT;tm++){
                unsigned ah[4];
                unsigned asw = swz((unsigned)((wm + tm*16 + lrow8)*128 + kb));
                ldsm4(ah, base + asw);
                #pragma unroll
                for (int t=0;t<2;t++){
                    int j0=2*t, j1=2*t+1;
                    mma_hf(acc[tm][j0], ah, BH[t][0], BH[t][2]);
                    mma_hf(acc[tm][j1], ah, BH[t][1], BH[t][3]);
                    if (DUAL){
                        mma_hf(acc[2+tm][j0], ah, BH[2+t][0], BH[2+t][2]);
                        mma_hf(acc[2+tm][j1], ah, BH[2+t][1], BH[2+t][3]);
                    }
                }
            }
        }
        __syncthreads();
    }

    if (!DUAL){
        #pragma unroll
        for (int tm=0;tm<4;tm++){
            int r = bm + wm + tm*16 + (lane>>2);
            #pragma unroll
            for (int j=0;j<4;j++){
                float* cc = acc[tm][j];
                int col = bn + wn + j*8 + (lane&3)*2;
                if (r < Mloc)
                    *(float2*)(C + (ll)(rowBase+r)*Ncols + col) = make_float2(cc[0],cc[1]);
                if (r+8 < Mloc)
                    *(float2*)(C + (ll)(rowBase+r+8)*Ncols + col) = make_float2(cc[2],cc[3]);
            }
        }
    } else {
        #pragma unroll
        for (int tm=0;tm<2;tm++){
            int r = bm + wm + tm*16 + (lane>>2);
            #pragma unroll
            for (int j=0;j<4;j++){
                float* gg = acc[tm][j];
                float* uu = acc[2+tm][j];
                float v0 = gg[0]*uu[0]/(1.f+__expf(-gg[0]));
                float v1 = gg[1]*uu[1]/(1.f+__expf(-gg[1]));
                float v2 = gg[2]*uu[2]/(1.f+__expf(-gg[2]));
                float v3 = gg[3]*uu[3]/(1.f+__expf(-gg[3]));
                int col = bn + wn + j*8 + (lane&3)*2;
                __half2 h0, h1;
                h0.x = __float2half_rn(v0); h0.y = __float2half_rn(v1);
                h1.x = __float2half_rn(v2); h1.y = __float2half_rn(v3);
                if (r < Mloc)
                    *(__half2*)(TH + (ll)(rowBase+r)*Ncols + col) = h0;
                if (r+8 < Mloc)
                    *(__half2*)(TH + (ll)(rowBase+r+8)*Ncols + col) = h1;
            }
        }
    }
}

__global__ void combine_rows(const float* __restrict__ enorm, const float* __restrict__ outnorm){
    int t = blockIdx.x, tid = threadIdx.x;
    int s0=g_slotof[2*t], s1=g_slotof[2*t+1], e0=g_topidx[2*t], e1=g_topidx[2*t+1];
    float gg0=g_topgate[2*t], gg1=g_topgate[2*t+1];
    float4 a = ((const float4*)(g_Oe+(ll)s0*DMODEL))[tid];
    float4 b = ((const float4*)(g_Oe+(ll)s1*DMODEL))[tid];
    float ssa=a.x*a.x+a.y*a.y+a.z*a.z+a.w*a.w, ssb=b.x*b.x+b.y*b.y+b.z*b.z+b.w*b.w;
    __shared__ float rA[8],rB[8],rC[8];
    for (int o=16;o;o>>=1){ ssa+=__shfl_xor_sync(~0u,ssa,o); ssb+=__shfl_xor_sync(~0u,ssb,o); }
    if ((tid&31)==0){ rA[tid>>5]=ssa; rB[tid>>5]=ssb; }
    __syncthreads();
    float ta=rA[0]+rA[1]+rA[2]+rA[3]+rA[4]+rA[5]+rA[6]+rA[7];
    float tb=rB[0]+rB[1]+rB[2]+rB[3]+rB[4]+rB[5]+rB[6]+rB[7];
    float r0=rsqrtf(ta*(1.f/DMODEL)+EPSF)*gg0, r1=rsqrtf(tb*(1.f/DMODEL)+EPSF)*gg1;
    float4 w0=((const float4*)(enorm+(ll)e0*DMODEL))[tid];
    float4 w1=((const float4*)(enorm+(ll)e1*DMODEL))[tid];
    float4 c = make_float4(a.x*r0*w0.x+b.x*r1*w1.x, a.y*r0*w0.y+b.y*r1*w1.y,
                           a.z*r0*w0.z+b.z*r1*w1.z, a.w*r0*w0.w+b.w*r1*w1.w);
    float ssc=c.x*c.x+c.y*c.y+c.z*c.z+c.w*c.w;
    for (int o=16;o;o>>=1) ssc+=__shfl_xor_sync(~0u,ssc,o);
    if ((tid&31)==0) rC[tid>>5]=ssc;
    __syncthreads();
    float tc=rC[0]+rC[1]+rC[2]+rC[3]+rC[4]+rC[5]+rC[6]+rC[7];
    float rc=rsqrtf(tc*(1.f/DMODEL)+EPSF);
    float4 wo=((const float4*)outnorm)[tid];
    float4 o4=make_float4(c.x*rc*wo.x, c.y*rc*wo.y, c.z*rc*wo.z, c.w*rc*wo.w);
    __half2 p0,p1;
    p0.x=__float2half_rn(o4.x); p0.y=__float2half_rn(o4.y);
    p1.x=__float2half_rn(o4.z); p1.y=__float2half_rn(o4.w);
    __half2* ph=(__half2*)(g_yHf+(ll)t*DMODEL);
    ph[2*tid]=p0; ph[2*tid+1]=p1;
}

extern "C" void kernel_launch(void* const* d_in, const int* in_sizes, int n_in,
                              void* d_out, int out_size)
{
    const float* s          = (const float*)d_in[0];
    const float* W_in       = (const float*)d_in[1];
    const float* in_norm_w  = (const float*)d_in[2];
    const float* Wr         = (const float*)d_in[3];
    const float* expert_bias= (const float*)d_in[4];
    const float* Wg         = (const float*)d_in[5];
    const float* Wu         = (const float*)d_in[6];
    const float* Wd         = (const float*)d_in[7];
    const float* enorm_w    = (const float*)d_in[8];
    const float* out_norm_w = (const float*)d_in[9];
    const float* W_out      = (const float*)d_in[10];
    float* out = (float*)d_out;

    cudaFuncSetAttribute(mm_bf, cudaFuncAttributeMaxDynamicSharedMemorySize, SMEM_BF);
    cudaFuncSetAttribute(mm_f16<1,1>, cudaFuncAttributeMaxDynamicSharedMemorySize, SMEM_HF);
    cudaFuncSetAttribute(mm_f16<0,1>, cudaFuncAttributeMaxDynamicSharedMemorySize, SMEM_HF);
    cudaFuncSetAttribute(mm_f16<0,0>, cudaFuncAttributeMaxDynamicSharedMemorySize, SMEM_HF);

    void* p;
    #define SYM(v,T,sname) cudaGetSymbolAddress(&p,sname); T* v=(T*)p;
    SYM(h_ptr,float,g_h) SYM(Oe_ptr,float,g_Oe)
    SYM(sH,bf,g_sH) SYM(sL,bf,g_sL)
    SYM(WinH,bf,g_WinH) SYM(WinL,bf,g_WinL)
    SYM(hHf,__half,g_hHf) SYM(yHf,__half,g_yHf)
    SYM(THf,__half,g_THf)
    SYM(WgF,__half,g_WgF) SYM(WuF,__half,g_WuF) SYM(WdF,__half,g_WdF) SYM(WoF,__half,g_WoF)
    SYM(off_ptr,int,g_off) SYM(ptok,int,g_pairtok)
    #undef SYM

    init_counts<<<1,32>>>();
    int nW = DMODEL*DMODEL/4, nE = NEXP*DFF*DMODEL/4;
    convert_hilo<<<(N_TOK*DMODEL/4+255)/256,256>>>(s, sH, sL, N_TOK*DMODEL/4);
    convert_hilo<<<(nW+255)/256,256>>>(W_in, WinH, WinL, nW);
    convert_f16<<<(nE+255)/256,256>>>(Wg, WgF, nE);
    convert_f16<<<(nE+255)/256,256>>>(Wu, WuF, nE);
    convert_f16<<<(nE+255)/256,256>>>(Wd, WdF, nE);
    convert_f16<<<(nW+255)/256,256>>>(W_out, WoF, nW);

    // h_pre = s @ W_in^T  (bf16 3-pass; protects router)
    mm_bf<<<dim3(N_TOK/128, DMODEL/128), 256, SMEM_BF>>>(
        sH, sL, WinH, WinL, h_ptr, N_TOK, DMODEL, DMODEL);
    rmsnorm_f16<<<N_TOK,256>>>(h_ptr, in_norm_w, h_ptr, hHf);
    router_kernel<<<(N_TOK*32)/256,256>>>(h_ptr, Wr, expert_bias);
    scan_offsets<<<1,32>>>();
    scatter_pairs<<<N_TOK/256,256>>>();

    // T = silu(h Wg^T) * (h Wu^T)  (fp16 1-pass, CTA 256x(64+64), flattened grid)
    mm_f16<1,1><<<dim3(NPAIR/256 + NEXP, DFF/64), 512, SMEM_HF>>>(
        hHf, WgF, WuF, nullptr, THf,
        0, DMODEL, DFF, off_ptr, ptok, (ll)DFF*DMODEL);

    // Oe = T @ Wd^T  (fp16 1-pass, CTA 128x256, flattened grid)
    mm_f16<0,1><<<dim3(NPAIR/128 + NEXP, DMODEL/256), 512, SMEM_HF>>>(
        THf, WdF, nullptr, Oe_ptr, nullptr,
        0, DFF, DMODEL, off_ptr, nullptr, (ll)DMODEL*DFF);

    combine_rows<<<N_TOK,256>>>(enorm_w, out_norm_w);

    // out = y @ W_out^T  (fp16 1-pass, dense)
    mm_f16<0,0><<<dim3(N_TOK/128, DMODEL/256), 512, SMEM_HF>>>(
        yHf, WoF, nullptr, out, nullptr,
        N_TOK, DMODEL, DMODEL, nullptr, nullptr, 0);
}

// round 13
// speedup vs baseline: 1.1503x; 1.1503x over previous
#include <cuda_runtime.h>
#include <cuda_bf16.h>
#include <cuda_fp16.h>

#define N_TOK 8192
#define DMODEL 1024
#define DFF 4096
#define NEXP 8
#define NPAIR (N_TOK * 2)
#define EPSF 1.1920928955078125e-07f
#define STAGE_BF 65536u
#define SMEM_BF (3 * 65536)
#define STAGE_HF 32768u
#define SMEM_HF (3 * 32768)
typedef __nv_bfloat16 bf;
typedef __nv_bfloat162 bf2;
typedef long long ll;

__device__ float g_h[(size_t)N_TOK * DMODEL];
__device__ float g_Oe[(size_t)NPAIR * DMODEL];
__device__ bf g_sH[(size_t)N_TOK*DMODEL], g_sL[(size_t)N_TOK*DMODEL];
__device__ bf g_WinH[(size_t)DMODEL*DMODEL], g_WinL[(size_t)DMODEL*DMODEL];
__device__ __half g_hHf[(size_t)N_TOK*DMODEL];
__device__ __half g_yHf[(size_t)N_TOK*DMODEL];
__device__ __half g_THf[(size_t)NPAIR*DFF];
__device__ __half g_WgF[(size_t)NEXP*DFF*DMODEL];
__device__ __half g_WuF[(size_t)NEXP*DFF*DMODEL];
__device__ __half g_WdF[(size_t)NEXP*DMODEL*DFF];
__device__ __half g_WoF[(size_t)DMODEL*DMODEL];
__device__ int g_cnt[NEXP], g_off[NEXP+1], g_cur[NEXP];
__device__ int g_pairtok[NPAIR], g_slotof[NPAIR], g_topidx[NPAIR];
__device__ float g_topgate[NPAIR];

__device__ __forceinline__ unsigned su32(const void* p){
    unsigned a; asm("{ .reg .u64 t; cvta.to.shared.u64 t, %1; cvt.u32.u64 %0, t; }":"=r"(a):"l"(p)); return a;
}
__device__ __forceinline__ void cp16(unsigned d, const void* s){
    asm volatile("cp.async.cg.shared.global [%0], [%1], 16;"::"r"(d),"l"(s));
}
__device__ __forceinline__ unsigned swz(unsigned off){ return off ^ ((off>>3)&0x70u); }
__device__ __forceinline__ void ldsm4(unsigned* r, unsigned a){
    asm volatile("ldmatrix.sync.aligned.m8n8.x4.shared.b16 {%0,%1,%2,%3}, [%4];"
        :"=r"(r[0]),"=r"(r[1]),"=r"(r[2]),"=r"(r[3]):"r"(a));
}
__device__ __forceinline__ void mma_bf(float* c, const unsigned* a, unsigned b0, unsigned b1){
    asm volatile("mma.sync.aligned.m16n8k16.row.col.f32.bf16.bf16.f32 "
        "{%0,%1,%2,%3},{%4,%5,%6,%7},{%8,%9},{%0,%1,%2,%3};"
        :"+f"(c[0]),"+f"(c[1]),"+f"(c[2]),"+f"(c[3])
        :"r"(a[0]),"r"(a[1]),"r"(a[2]),"r"(a[3]),"r"(b0),"r"(b1));
}
__device__ __forceinline__ void mma_hf(float* c, const unsigned* a, unsigned b0, unsigned b1){
    asm volatile("mma.sync.aligned.m16n8k16.row.col.f32.f16.f16.f32 "
        "{%0,%1,%2,%3},{%4,%5,%6,%7},{%8,%9},{%0,%1,%2,%3};"
        :"+f"(c[0]),"+f"(c[1]),"+f"(c[2]),"+f"(c[3])
        :"r"(a[0]),"r"(a[1]),"r"(a[2]),"r"(a[3]),"r"(b0),"r"(b1));
}
__device__ __forceinline__ void split2(float x, bf& h, bf& l){
    h = __float2bfloat16(x); l = __float2bfloat16(x - __bfloat162float(h));
}

__global__ void init_counts(){ if (threadIdx.x < NEXP) g_cnt[threadIdx.x] = 0; }
__global__ void scan_offsets(){
    if (threadIdx.x == 0){ int s=0; for(int e=0;e<NEXP;e++){ g_off[e]=s; s+=g_cnt[e]; } g_off[NEXP]=s; }
    if (threadIdx.x < NEXP) g_cur[threadIdx.x] = 0;
}
__global__ void scatter_pairs(){
    int t = blockIdx.x*blockDim.x + threadIdx.x; if (t >= N_TOK) return;
    for (int k=0;k<2;k++){
        int e = g_topidx[2*t+k];
        int slot = g_off[e] + atomicAdd(&g_cur[e],1);
        g_pairtok[slot] = t; g_slotof[2*t+k] = slot;
    }
}
__global__ void convert_hilo(const float* __restrict__ x, bf* __restrict__ h, bf* __restrict__ l, int n4){
    int i = blockIdx.x*blockDim.x + threadIdx.x; if (i >= n4) return;
    float4 v = ((const float4*)x)[i];
    bf2 p0,p1,q0,q1;
    split2(v.x,p0.x,q0.x); split2(v.y,p0.y,q0.y); split2(v.z,p1.x,q1.x); split2(v.w,p1.y,q1.y);
    ((bf2*)h)[2*i]=p0; ((bf2*)h)[2*i+1]=p1; ((bf2*)l)[2*i]=q0; ((bf2*)l)[2*i+1]=q1;
}
__global__ void convert_f16(const float* __restrict__ x, __half* __restrict__ o, int n4){
    int i = blockIdx.x*blockDim.x + threadIdx.x; if (i >= n4) return;
    float4 v = ((const float4*)x)[i];
    __half2 p0, p1;
    p0.x = __float2half_rn(v.x); p0.y = __float2half_rn(v.y);
    p1.x = __float2half_rn(v.z); p1.y = __float2half_rn(v.w);
    ((__half2*)o)[2*i]=p0; ((__half2*)o)[2*i+1]=p1;
}
// one launch converts Wg, Wu, Wd (blockIdx.y picks the tensor)
__global__ void convert_f16_3(const float* __restrict__ a, __half* __restrict__ oa,
                              const float* __restrict__ b, __half* __restrict__ ob,
                              const float* __restrict__ c, __half* __restrict__ oc, int n4){
    int i = blockIdx.x*blockDim.x + threadIdx.x; if (i >= n4) return;
    const float* x; __half* o;
    if (blockIdx.y == 0){ x=a; o=oa; } else if (blockIdx.y == 1){ x=b; o=ob; } else { x=c; o=oc; }
    float4 v = ((const float4*)x)[i];
    __half2 p0, p1;
    p0.x = __float2half_rn(v.x); p0.y = __float2half_rn(v.y);
    p1.x = __float2half_rn(v.z); p1.y = __float2half_rn(v.w);
    ((__half2*)o)[2*i]=p0; ((__half2*)o)[2*i+1]=p1;
}
__global__ void rmsnorm_f16(const float* __restrict__ X, const float* __restrict__ w,
                            float* __restrict__ Y, __half* __restrict__ YH){
    int row = blockIdx.x, tid = threadIdx.x;
    float4 v = ((const float4*)(X + (ll)row*DMODEL))[tid];
    float ss = v.x*v.x+v.y*v.y+v.z*v.z+v.w*v.w;
    __shared__ float red[8];
    for (int o=16;o;o>>=1) ss += __shfl_xor_sync(~0u, ss, o);
    if ((tid&31)==0) red[tid>>5]=ss;
    __syncthreads();
    float tot = red[0]+red[1]+red[2]+red[3]+red[4]+red[5]+red[6]+red[7];
    float r = rsqrtf(tot*(1.0f/DMODEL)+EPSF);
    float4 wv = ((const float4*)w)[tid];
    float4 o4 = make_float4(v.x*r*wv.x, v.y*r*wv.y, v.z*r*wv.z, v.w*r*wv.w);
    ((float4*)(Y + (ll)row*DMODEL))[tid] = o4;
    __half2 p0,p1;
    p0.x = __float2half_rn(o4.x); p0.y = __float2half_rn(o4.y);
    p1.x = __float2half_rn(o4.z); p1.y = __float2half_rn(o4.w);
    __half2* ph=(__half2*)(YH+(ll)row*DMODEL);
    ph[2*tid]=p0; ph[2*tid+1]=p1;
}
__global__ void router_kernel(const float* __restrict__ h, const float* __restrict__ Wr, const float* __restrict__ bias){
    int warp = (blockIdx.x*blockDim.x+threadIdx.x)>>5, lane = threadIdx.x&31;
    if (warp >= N_TOK) return;
    const float* hr = h + (ll)warp*DMODEL;
    float acc[NEXP];
    #pragma unroll
    for (int e=0;e<NEXP;e++) acc[e]=0.f;
    for (int d=lane; d<DMODEL; d+=32){
        float hv = hr[d];
        #pragma unroll
        for (int e=0;e<NEXP;e++) acc[e] += hv*Wr[e*DMODEL+d];
    }
    #pragma unroll
    for (int e=0;e<NEXP;e++)
        for (int o=16;o;o>>=1) acc[e] += __shfl_xor_sync(~0u, acc[e], o);
    if (lane==0){
        float b0=-1e30f,b1=-1e30f; int i0=0,i1=0;
        #pragma unroll
        for (int e=0;e<NEXP;e++){
            float v = acc[e]+bias[e];
            if (v>b0){ b1=b0;i1=i0;b0=v;i0=e; } else if (v>b1){ b1=v;i1=e; }
        }
        float m=fmaxf(acc[i0],acc[i1]);
        float e0=expf(acc[i0]-m), e1=expf(acc[i1]-m), inv=1.f/(e0+e1);
        g_topidx[2*warp]=i0; g_topidx[2*warp+1]=i1;
        g_topgate[2*warp]=e0*inv; g_topgate[2*warp+1]=e1*inv;
        atomicAdd(&g_cnt[i0],1); atomicAdd(&g_cnt[i1],1);
    }
}

// ---------- bf16 3-pass dense GEMM (in-proj; protects router), 3-stage, 1 sync/iter ----------
__global__ __launch_bounds__(256) void mm_bf(
    const bf* __restrict__ Ah, const bf* __restrict__ Al,
    const bf* __restrict__ B0h, const bf* __restrict__ B0l,
    float* __restrict__ C, int Mdense, int K, int Ncols)
{
    extern __shared__ char dsm[];
    int Mloc = Mdense;
    int bm = blockIdx.x*128; if (bm >= Mloc) return;
    int bn = blockIdx.y*128;
    unsigned sb = su32(dsm);
    int tid = threadIdx.x;
    int aslot = tid&7, arow0 = tid>>3;
    int w = tid>>5, lane = tid&31;
    int wm = (w>>2)*64, wn = (w&3)*32;
    float acc[4][4][4];
    #pragma unroll
    for (int i=0;i<4;i++)
        #pragma unroll
        for (int j=0;j<4;j++)
            #pragma unroll
            for (int q=0;q<4;q++) acc[i][j][q] = 0.f;

    int total = K>>6;
    auto load = [&](int kt){
        unsigned base = sb + (unsigned)(kt%3)*STAGE_BF;
        int ke = kt*64 + aslot*8;
        #pragma unroll
        for (int j=0;j<4;j++){
            int r = arow0 + 32*j;
            unsigned sw = swz((unsigned)(r*128 + aslot*16));
            int ar = bm + r;
            cp16(base+sw,        Ah + (ll)ar*K + ke);
            cp16(base+16384u+sw, Al + (ll)ar*K + ke);
            int br = bn + r;
            cp16(base+32768u+sw, B0h + (ll)br*K + ke);
            cp16(base+49152u+sw, B0l + (ll)br*K + ke);
        }
        asm volatile("cp.async.commit_group;":::"memory");
    };
    if (0 < total) load(0);
    if (1 < total) load(1);
    for (int c = 0; c < total; ++c){
        if (c+1 < total) asm volatile("cp.async.wait_group 1;":::"memory");
        else             asm volatile("cp.async.wait_group 0;":::"memory");
        __syncthreads();

        unsigned base = sb + (unsigned)(c%3)*STAGE_BF;
        int lrow8 = ((lane>>3)&1)*8 + (lane&7);
        #pragma unroll
        for (int ks=0; ks<4; ks++){
            int kb = ks*32 + (lane>>4)*16;
            unsigned BH[2][4], BL[2][4];
            #pragma unroll
            for (int t=0;t<2;t++){
                unsigned sw = swz((unsigned)((wn + t*16 + lrow8)*128 + kb));
                ldsm4(BH[t], base + 32768u + sw);
                ldsm4(BL[t], base + 49152u + sw);
            }
            #pragma unroll
            for (int tm=0;tm<4;tm++){
                unsigned ah[4], al[4];
                unsigned asw = swz((unsigned)((wm + tm*16 + lrow8)*128 + kb));
                ldsm4(ah, base + asw);
                ldsm4(al, base + 16384u + asw);
                #pragma unroll
                for (int t=0;t<2;t++){
                    int j0=2*t, j1=2*t+1;
                    mma_bf(acc[tm][j0], ah, BH[t][0], BH[t][2]);
                    mma_bf(acc[tm][j0], ah, BL[t][0], BL[t][2]);
                    mma_bf(acc[tm][j0], al, BH[t][0], BH[t][2]);
                    mma_bf(acc[tm][j1], ah, BH[t][1], BH[t][3]);
                    mma_bf(acc[tm][j1], ah, BL[t][1], BL[t][3]);
                    mma_bf(acc[tm][j1], al, BH[t][1], BH[t][3]);
                }
            }
        }
        if (c+2 < total) load(c+2);
    }
    #pragma unroll
    for (int tm=0;tm<4;tm++){
        int r = bm + wm + tm*16 + (lane>>2);
        #pragma unroll
        for (int j=0;j<4;j++){
            float* cc = acc[tm][j];
            int col = bn + wn + j*8 + (lane&3)*2;
            *(float2*)(C + (ll)r*Ncols + col) = make_float2(cc[0],cc[1]);
            *(float2*)(C + (ll)(r+8)*Ncols + col) = make_float2(cc[2],cc[3]);
        }
    }
}

// ---------- fp16 1-pass GEMM, 3-stage pipeline, 1 sync/iter, flattened grouped grid ----------
// DUAL=1: B = 64 gate + 64 up rows, epilogue silu(g)*u -> single fp16 TH.
// GROUPED=1: blockIdx.x scans d_off to find (expert, m-tile).
template<int DUAL, int GROUPED>
__global__ __launch_bounds__(256, 2) void mm_f16(
    const __half* __restrict__ Ah,
    const __half* __restrict__ B0, const __half* __restrict__ B1,
    float* __restrict__ C, __half* __restrict__ TH,
    int Mdense, int K, int Ncols,
    const int* __restrict__ d_off, const int* __restrict__ pairtok, ll strideB)
{
    extern __shared__ char dsm[];
    int rowBase = 0, Mloc = Mdense, bm;
    const __half *b0 = B0, *b1 = B1;
    if (GROUPED){
        int idx = blockIdx.x, e = 0;
        int base0 = 0, m = 0;
        #pragma unroll 1
        for (; e < NEXP; e++){
            base0 = d_off[e]; m = d_off[e+1]-base0;
            int nt = (m+127)>>7;
            if (idx < nt) break;
            idx -= nt;
        }
        if (e == NEXP) return;
        rowBase = base0; Mloc = m; bm = idx*128;
        b0 += (ll)e*strideB;
        if (DUAL) b1 += (ll)e*strideB;
    } else {
        bm = blockIdx.x*128;
        if (bm >= Mloc) return;
    }
    int bn = blockIdx.y*(DUAL?64:128);

    unsigned sb = su32(dsm);
    int tid = threadIdx.x;
    int aslot = tid&7, arow0 = tid>>3;
    int ga[4];
    #pragma unroll
    for (int j=0;j<4;j++){
        int lr = bm + arow0 + 32*j; if (lr > Mloc-1) lr = Mloc-1;
        ga[j] = (GROUPED && DUAL) ? pairtok[rowBase+lr] : (rowBase+lr);
    }
    int w = tid>>5, lane = tid&31;
    int wm = DUAL ? (w>>1)*32 : (w>>2)*64;
    int wn = (DUAL ? (w&1) : (w&3))*32;
    constexpr int MT = DUAL ? 2 : 4;
    constexpr int NB = DUAL ? 4 : 2;

    float acc[4][4][4];   // dual: [0..1]=gate, [2..3]=up
    #pragma unroll
    for (int i=0;i<4;i++)
        #pragma unroll
        for (int j=0;j<4;j++)
            #pragma unroll
            for (int q=0;q<4;q++) acc[i][j][q] = 0.f;

    int total = K>>6;
    auto load = [&](int kt){
        unsigned base = sb + (unsigned)(kt%3)*STAGE_HF;
        int ke = kt*64 + aslot*8;
        #pragma unroll
        for (int j=0;j<4;j++){
            int r = arow0 + 32*j;
            unsigned sw = swz((unsigned)(r*128 + aslot*16));
            cp16(base+sw, Ah + (ll)ga[j]*K + ke);
            const __half* bp; int br;
            if (DUAL && r >= 64){ bp = b1; br = bn + r - 64; }
            else                { bp = b0; br = bn + r; }
            cp16(base+16384u+sw, bp + (ll)br*K + ke);
        }
        asm volatile("cp.async.commit_group;":::"memory");
    };
    if (0 < total) load(0);
    if (1 < total) load(1);
    for (int c = 0; c < total; ++c){
        if (c+1 < total) asm volatile("cp.async.wait_group 1;":::"memory");
        else             asm volatile("cp.async.wait_group 0;":::"memory");
        __syncthreads();

        unsigned base = sb + (unsigned)(c%3)*STAGE_HF;
        int lrow8 = ((lane>>3)&1)*8 + (lane&7);
        #pragma unroll
        for (int ks=0; ks<4; ks++){
            int kb = ks*32 + (lane>>4)*16;
            unsigned BH[NB][4];
            #pragma unroll
            for (int t=0;t<NB;t++){
                int nb = (DUAL && t>=2) ? (64 + wn + (t-2)*16) : (wn + t*16);
                ldsm4(BH[t], base + 16384u + swz((unsigned)((nb + lrow8)*128 + kb)));
            }
            #pragma unroll
            for (int tm=0;tm<MT;tm++){
                unsigned ah[4];
                unsigned asw = swz((unsigned)((wm + tm*16 + lrow8)*128 + kb));
                ldsm4(ah, base + asw);
                #pragma unroll
                for (int t=0;t<2;t++){
                    int j0=2*t, j1=2*t+1;
                    mma_hf(acc[tm][j0], ah, BH[t][0], BH[t][2]);
                    mma_hf(acc[tm][j1], ah, BH[t][1], BH[t][3]);
                    if (DUAL){
                        mma_hf(acc[2+tm][j0], ah, BH[2+t][0], BH[2+t][2]);
                        mma_hf(acc[2+tm][j1], ah, BH[2+t][1], BH[2+t][3]);
                    }
                }
            }
        }
        if (c+2 < total) load(c+2);
    }

    if (!DUAL){
        #pragma unroll
        for (int tm=0;tm<4;tm++){
            int r = bm + wm + tm*16 + (lane>>2);
            #pragma unroll
            for (int j=0;j<4;j++){
                float* cc = acc[tm][j];
                int col = bn + wn + j*8 + (lane&3)*2;
                if (r < Mloc)
                    *(float2*)(C + (ll)(rowBase+r)*Ncols + col) = make_float2(cc[0],cc[1]);
                if (r+8 < Mloc)
                    *(float2*)(C + (ll)(rowBase+r+8)*Ncols + col) = make_float2(cc[2],cc[3]);
            }
        }
    } else {
        #pragma unroll
        for (int tm=0;tm<2;tm++){
            int r = bm + wm + tm*16 + (lane>>2);
            #pragma unroll
            for (int j=0;j<4;j++){
                float* gg = acc[tm][j];
                float* uu = acc[2+tm][j];
                float v0 = gg[0]*uu[0]/(1.f+__expf(-gg[0]));
                float v1 = gg[1]*uu[1]/(1.f+__expf(-gg[1]));
                float v2 = gg[2]*uu[2]/(1.f+__expf(-gg[2]));
                float v3 = gg[3]*uu[3]/(1.f+__expf(-gg[3]));
                int col = bn + wn + j*8 + (lane&3)*2;
                __half2 h0, h1;
                h0.x = __float2half_rn(v0); h0.y = __float2half_rn(v1);
                h1.x = __float2half_rn(v2); h1.y = __float2half_rn(v3);
                if (r < Mloc)
                    *(__half2*)(TH + (ll)(rowBase+r)*Ncols + col) = h0;
                if (r+8 < Mloc)
                    *(__half2*)(TH + (ll)(rowBase+r+8)*Ncols + col) = h1;
            }
        }
    }
}

__global__ void combine_rows(const float* __restrict__ enorm, const float* __restrict__ outnorm){
    int t = blockIdx.x, tid = threadIdx.x;
    int s0=g_slotof[2*t], s1=g_slotof[2*t+1], e0=g_topidx[2*t], e1=g_topidx[2*t+1];
    float gg0=g_topgate[2*t], gg1=g_topgate[2*t+1];
    float4 a = ((const float4*)(g_Oe+(ll)s0*DMODEL))[tid];
    float4 b = ((const float4*)(g_Oe+(ll)s1*DMODEL))[tid];
    float ssa=a.x*a.x+a.y*a.y+a.z*a.z+a.w*a.w, ssb=b.x*b.x+b.y*b.y+b.z*b.z+b.w*b.w;
    __shared__ float rA[8],rB[8],rC[8];
    for (int o=16;o;o>>=1){ ssa+=__shfl_xor_sync(~0u,ssa,o); ssb+=__shfl_xor_sync(~0u,ssb,o); }
    if ((tid&31)==0){ rA[tid>>5]=ssa; rB[tid>>5]=ssb; }
    __syncthreads();
    float ta=rA[0]+rA[1]+rA[2]+rA[3]+rA[4]+rA[5]+rA[6]+rA[7];
    float tb=rB[0]+rB[1]+rB[2]+rB[3]+rB[4]+rB[5]+rB[6]+rB[7];
    float r0=rsqrtf(ta*(1.f/DMODEL)+EPSF)*gg0, r1=rsqrtf(tb*(1.f/DMODEL)+EPSF)*gg1;
    float4 w0=((const float4*)(enorm+(ll)e0*DMODEL))[tid];
    float4 w1=((const float4*)(enorm+(ll)e1*DMODEL))[tid];
    float4 c = make_float4(a.x*r0*w0.x+b.x*r1*w1.x, a.y*r0*w0.y+b.y*r1*w1.y,
                           a.z*r0*w0.z+b.z*r1*w1.z, a.w*r0*w0.w+b.w*r1*w1.w);
    float ssc=c.x*c.x+c.y*c.y+c.z*c.z+c.w*c.w;
    for (int o=16;o;o>>=1) ssc+=__shfl_xor_sync(~0u,ssc,o);
    if ((tid&31)==0) rC[tid>>5]=ssc;
    __syncthreads();
    float tc=rC[0]+rC[1]+rC[2]+rC[3]+rC[4]+rC[5]+rC[6]+rC[7];
    float rc=rsqrtf(tc*(1.f/DMODEL)+EPSF);
    float4 wo=((const float4*)outnorm)[tid];
    float4 o4=make_float4(c.x*rc*wo.x, c.y*rc*wo.y, c.z*rc*wo.z, c.w*rc*wo.w);
    __half2 p0,p1;
    p0.x=__float2half_rn(o4.x); p0.y=__float2half_rn(o4.y);
    p1.x=__float2half_rn(o4.z); p1.y=__float2half_rn(o4.w);
    __half2* ph=(__half2*)(g_yHf+(ll)t*DMODEL);
    ph[2*tid]=p0; ph[2*tid+1]=p1;
}

extern "C" void kernel_launch(void* const* d_in, const int* in_sizes, int n_in,
                              void* d_out, int out_size)
{
    const float* s          = (const float*)d_in[0];
    const float* W_in       = (const float*)d_in[1];
    const float* in_norm_w  = (const float*)d_in[2];
    const float* Wr         = (const float*)d_in[3];
    const float* expert_bias= (const float*)d_in[4];
    const float* Wg         = (const float*)d_in[5];
    const float* Wu         = (const float*)d_in[6];
    const float* Wd         = (const float*)d_in[7];
    const float* enorm_w    = (const float*)d_in[8];
    const float* out_norm_w = (const float*)d_in[9];
    const float* W_out      = (const float*)d_in[10];
    float* out = (float*)d_out;

    cudaFuncSetAttribute(mm_bf, cudaFuncAttributeMaxDynamicSharedMemorySize, SMEM_BF);
    cudaFuncSetAttribute(mm_f16<1,1>, cudaFuncAttributeMaxDynamicSharedMemorySize, SMEM_HF);
    cudaFuncSetAttribute(mm_f16<0,1>, cudaFuncAttributeMaxDynamicSharedMemorySize, SMEM_HF);
    cudaFuncSetAttribute(mm_f16<0,0>, cudaFuncAttributeMaxDynamicSharedMemorySize, SMEM_HF);

    void* p;
    #define SYM(v,T,sname) cudaGetSymbolAddress(&p,sname); T* v=(T*)p;
    SYM(h_ptr,float,g_h) SYM(Oe_ptr,float,g_Oe)
    SYM(sH,bf,g_sH) SYM(sL,bf,g_sL)
    SYM(WinH,bf,g_WinH) SYM(WinL,bf,g_WinL)
    SYM(hHf,__half,g_hHf) SYM(yHf,__half,g_yHf)
    SYM(THf,__half,g_THf)
    SYM(WgF,__half,g_WgF) SYM(WuF,__half,g_WuF) SYM(WdF,__half,g_WdF) SYM(WoF,__half,g_WoF)
    SYM(off_ptr,int,g_off) SYM(ptok,int,g_pairtok)
    #undef SYM

    init_counts<<<1,32>>>();
    int nW = DMODEL*DMODEL/4, nE = NEXP*DFF*DMODEL/4;
    convert_hilo<<<(N_TOK*DMODEL/4+255)/256,256>>>(s, sH, sL, N_TOK*DMODEL/4);
    convert_hilo<<<(nW+255)/256,256>>>(W_in, WinH, WinL, nW);
    convert_f16_3<<<dim3((nE+255)/256, 3), 256>>>(Wg, WgF, Wu, WuF, Wd, WdF, nE);
    convert_f16<<<(nW+255)/256,256>>>(W_out, WoF, nW);

    // h_pre = s @ W_in^T  (bf16 3-pass; protects router)
    mm_bf<<<dim3(N_TOK/128, DMODEL/128), 256, SMEM_BF>>>(
        sH, sL, WinH, WinL, h_ptr, N_TOK, DMODEL, DMODEL);
    rmsnorm_f16<<<N_TOK,256>>>(h_ptr, in_norm_w, h_ptr, hHf);
    router_kernel<<<(N_TOK*32)/256,256>>>(h_ptr, Wr, expert_bias);
    scan_offsets<<<1,32>>>();
    scatter_pairs<<<N_TOK/256,256>>>();

    // T = silu(h Wg^T) * (h Wu^T)  (fp16 1-pass, flattened grouped grid)
    mm_f16<1,1><<<dim3(NPAIR/128 + NEXP, DFF/64), 256, SMEM_HF>>>(
        hHf, WgF, WuF, nullptr, THf,
        0, DMODEL, DFF, off_ptr, ptok, (ll)DFF*DMODEL);

    // Oe = T @ Wd^T  (fp16 1-pass, flattened grouped grid)
    mm_f16<0,1><<<dim3(NPAIR/128 + NEXP, DMODEL/128), 256, SMEM_HF>>>(
        THf, WdF, nullptr, Oe_ptr, nullptr,
        0, DFF, DMODEL, off_ptr, nullptr, (ll)DMODEL*DFF);

    combine_rows<<<N_TOK,256>>>(enorm_w, out_norm_w);

    // out = y @ W_out^T  (fp16 1-pass, dense)
    mm_f16<0,0><<<dim3(N_TOK/128, DMODEL/128), 256, SMEM_HF>>>(
        yHf, WoF, nullptr, out, nullptr,
        N_TOK, DMODEL, DMODEL, nullptr, nullptr, 0);
}

// round 14
// speedup vs baseline: 1.1588x; 1.0074x over previous
#include <cuda_runtime.h>
#include <cuda_bf16.h>
#include <cuda_fp16.h>

#define N_TOK 8192
#define DMODEL 1024
#define DFF 4096
#define NEXP 8
#define NPAIR (N_TOK * 2)
#define EPSF 1.1920928955078125e-07f
#define STAGE_BF 65536u
#define SMEM_BF (3 * 65536)
#define STAGE_HF 32768u
#define SMEM_HF (3 * 32768)
typedef __nv_bfloat16 bf;
typedef __nv_bfloat162 bf2;
typedef long long ll;

__device__ float g_h[(size_t)N_TOK * DMODEL];
__device__ float g_Oe[(size_t)NPAIR * DMODEL];
__device__ bf g_sH[(size_t)N_TOK*DMODEL], g_sL[(size_t)N_TOK*DMODEL];
__device__ bf g_WinH[(size_t)DMODEL*DMODEL], g_WinL[(size_t)DMODEL*DMODEL];
__device__ __half g_hHf[(size_t)N_TOK*DMODEL];
__device__ __half g_yHf[(size_t)N_TOK*DMODEL];
__device__ __half g_THf[(size_t)NPAIR*DFF];
__device__ __half g_WgF[(size_t)NEXP*DFF*DMODEL];
__device__ __half g_WuF[(size_t)NEXP*DFF*DMODEL];
__device__ __half g_WdF[(size_t)NEXP*DMODEL*DFF];
__device__ __half g_WoF[(size_t)DMODEL*DMODEL];
__device__ int g_cnt[NEXP], g_off[NEXP+1], g_cur[NEXP];
__device__ int g_pairtok[NPAIR], g_slotof[NPAIR], g_topidx[NPAIR];
__device__ float g_topgate[NPAIR];

__device__ __forceinline__ unsigned su32(const void* p){
    unsigned a; asm("{ .reg .u64 t; cvta.to.shared.u64 t, %1; cvt.u32.u64 %0, t; }":"=r"(a):"l"(p)); return a;
}
__device__ __forceinline__ void cp16(unsigned d, const void* s){
    asm volatile("cp.async.cg.shared.global [%0], [%1], 16;"::"r"(d),"l"(s));
}
__device__ __forceinline__ unsigned swz(unsigned off){ return off ^ ((off>>3)&0x70u); }
__device__ __forceinline__ void ldsm4(unsigned* r, unsigned a){
    asm volatile("ldmatrix.sync.aligned.m8n8.x4.shared.b16 {%0,%1,%2,%3}, [%4];"
        :"=r"(r[0]),"=r"(r[1]),"=r"(r[2]),"=r"(r[3]):"r"(a));
}
__device__ __forceinline__ void mma_bf(float* c, const unsigned* a, unsigned b0, unsigned b1){
    asm volatile("mma.sync.aligned.m16n8k16.row.col.f32.bf16.bf16.f32 "
        "{%0,%1,%2,%3},{%4,%5,%6,%7},{%8,%9},{%0,%1,%2,%3};"
        :"+f"(c[0]),"+f"(c[1]),"+f"(c[2]),"+f"(c[3])
        :"r"(a[0]),"r"(a[1]),"r"(a[2]),"r"(a[3]),"r"(b0),"r"(b1));
}
__device__ __forceinline__ void mma_hf(float* c, const unsigned* a, unsigned b0, unsigned b1){
    asm volatile("mma.sync.aligned.m16n8k16.row.col.f32.f16.f16.f32 "
        "{%0,%1,%2,%3},{%4,%5,%6,%7},{%8,%9},{%0,%1,%2,%3};"
        :"+f"(c[0]),"+f"(c[1]),"+f"(c[2]),"+f"(c[3])
        :"r"(a[0]),"r"(a[1]),"r"(a[2]),"r"(a[3]),"r"(b0),"r"(b1));
}
__device__ __forceinline__ void split2(float x, bf& h, bf& l){
    h = __float2bfloat16(x); l = __float2bfloat16(x - __bfloat162float(h));
}

__global__ void init_counts(){ if (threadIdx.x < NEXP) g_cnt[threadIdx.x] = 0; }
__global__ void scan_offsets(){
    if (threadIdx.x == 0){ int s=0; for(int e=0;e<NEXP;e++){ g_off[e]=s; s+=g_cnt[e]; } g_off[NEXP]=s; }
    if (threadIdx.x < NEXP) g_cur[threadIdx.x] = 0;
}
__global__ void scatter_pairs(){
    int t = blockIdx.x*blockDim.x + threadIdx.x; if (t >= N_TOK) return;
    for (int k=0;k<2;k++){
        int e = g_topidx[2*t+k];
        int slot = g_off[e] + atomicAdd(&g_cur[e],1);
        g_pairtok[slot] = t; g_slotof[2*t+k] = slot;
    }
}
// one launch converts Wg, Wu, Wd (blockIdx.y picks the tensor)
__global__ void convert_f16_3(const float* __restrict__ a, __half* __restrict__ oa,
                              const float* __restrict__ b, __half* __restrict__ ob,
                              const float* __restrict__ c, __half* __restrict__ oc, int n4){
    int i = blockIdx.x*blockDim.x + threadIdx.x; if (i >= n4) return;
    const float* x; __half* o;
    if (blockIdx.y == 0){ x=a; o=oa; } else if (blockIdx.y == 1){ x=b; o=ob; } else { x=c; o=oc; }
    float4 v = ((const float4*)x)[i];
    __half2 p0, p1;
    p0.x = __float2half_rn(v.x); p0.y = __float2half_rn(v.y);
    p1.x = __float2half_rn(v.z); p1.y = __float2half_rn(v.w);
    ((__half2*)o)[2*i]=p0; ((__half2*)o)[2*i+1]=p1;
}
// one launch: y=0 s->hilo, y=1 W_in->hilo, y=2 W_out->f16
__global__ void convert_misc(const float* __restrict__ s, bf* __restrict__ sH, bf* __restrict__ sL,
                             const float* __restrict__ Win, bf* __restrict__ WinH, bf* __restrict__ WinL,
                             const float* __restrict__ Wout, __half* __restrict__ WoF){
    int i = blockIdx.x*blockDim.x + threadIdx.x;
    if (blockIdx.y == 0){
        if (i >= N_TOK*DMODEL/4) return;
        float4 v = ((const float4*)s)[i];
        bf2 p0,p1,q0,q1;
        split2(v.x,p0.x,q0.x); split2(v.y,p0.y,q0.y); split2(v.z,p1.x,q1.x); split2(v.w,p1.y,q1.y);
        ((bf2*)sH)[2*i]=p0; ((bf2*)sH)[2*i+1]=p1; ((bf2*)sL)[2*i]=q0; ((bf2*)sL)[2*i+1]=q1;
    } else if (blockIdx.y == 1){
        if (i >= DMODEL*DMODEL/4) return;
        float4 v = ((const float4*)Win)[i];
        bf2 p0,p1,q0,q1;
        split2(v.x,p0.x,q0.x); split2(v.y,p0.y,q0.y); split2(v.z,p1.x,q1.x); split2(v.w,p1.y,q1.y);
        ((bf2*)WinH)[2*i]=p0; ((bf2*)WinH)[2*i+1]=p1; ((bf2*)WinL)[2*i]=q0; ((bf2*)WinL)[2*i+1]=q1;
    } else {
        if (i >= DMODEL*DMODEL/4) return;
        float4 v = ((const float4*)Wout)[i];
        __half2 p0, p1;
        p0.x = __float2half_rn(v.x); p0.y = __float2half_rn(v.y);
        p1.x = __float2half_rn(v.z); p1.y = __float2half_rn(v.w);
        ((__half2*)WoF)[2*i]=p0; ((__half2*)WoF)[2*i+1]=p1;
    }
}
// fused: rmsnorm(h_pre) -> hHf  +  router logits/top-2/gates/counts (fp32 exact path)
__global__ void rmsnorm_router(const float* __restrict__ X, const float* __restrict__ w,
                               __half* __restrict__ YH,
                               const float* __restrict__ Wr, const float* __restrict__ bias){
    int row = blockIdx.x, tid = threadIdx.x;   // 256 threads
    float4 v = ((const float4*)(X + (ll)row*DMODEL))[tid];
    float ss = v.x*v.x+v.y*v.y+v.z*v.z+v.w*v.w;
    __shared__ float red[8];
    __shared__ float rlog[8][NEXP];
    for (int o=16;o;o>>=1) ss += __shfl_xor_sync(~0u, ss, o);
    if ((tid&31)==0) red[tid>>5]=ss;
    __syncthreads();
    float tot = red[0]+red[1]+red[2]+red[3]+red[4]+red[5]+red[6]+red[7];
    float r = rsqrtf(tot*(1.0f/DMODEL)+EPSF);
    float4 wv = ((const float4*)w)[tid];
    float4 o4 = make_float4(v.x*r*wv.x, v.y*r*wv.y, v.z*r*wv.z, v.w*r*wv.w);
    __half2 p0,p1;
    p0.x = __float2half_rn(o4.x); p0.y = __float2half_rn(o4.y);
    p1.x = __float2half_rn(o4.z); p1.y = __float2half_rn(o4.w);
    __half2* ph=(__half2*)(YH+(ll)row*DMODEL);
    ph[2*tid]=p0; ph[2*tid+1]=p1;
    // router partials: each thread owns 4 dims
    float part[NEXP];
    #pragma unroll
    for (int e=0;e<NEXP;e++){
        float4 wr = ((const float4*)(Wr + e*DMODEL))[tid];
        part[e] = o4.x*wr.x + o4.y*wr.y + o4.z*wr.z + o4.w*wr.w;
    }
    #pragma unroll
    for (int e=0;e<NEXP;e++)
        for (int o=16;o;o>>=1) part[e] += __shfl_xor_sync(~0u, part[e], o);
    if ((tid&31)==0){
        #pragma unroll
        for (int e=0;e<NEXP;e++) rlog[tid>>5][e] = part[e];
    }
    __syncthreads();
    if (tid == 0){
        float acc[NEXP];
        #pragma unroll
        for (int e=0;e<NEXP;e++){
            float sum = 0.f;
            #pragma unroll
            for (int q=0;q<8;q++) sum += rlog[q][e];
            acc[e] = sum;
        }
        float b0=-1e30f,b1=-1e30f; int i0=0,i1=0;
        #pragma unroll
        for (int e=0;e<NEXP;e++){
            float vv = acc[e]+bias[e];
            if (vv>b0){ b1=b0;i1=i0;b0=vv;i0=e; } else if (vv>b1){ b1=vv;i1=e; }
        }
        float m=fmaxf(acc[i0],acc[i1]);
        float e0=expf(acc[i0]-m), e1=expf(acc[i1]-m), inv=1.f/(e0+e1);
        g_topidx[2*row]=i0; g_topidx[2*row+1]=i1;
        g_topgate[2*row]=e0*inv; g_topgate[2*row+1]=e1*inv;
        atomicAdd(&g_cnt[i0],1); atomicAdd(&g_cnt[i1],1);
    }
}

// ---------- bf16 3-pass dense GEMM (in-proj; protects router), 3-stage, 1 sync/iter ----------
__global__ __launch_bounds__(256) void mm_bf(
    const bf* __restrict__ Ah, const bf* __restrict__ Al,
    const bf* __restrict__ B0h, const bf* __restrict__ B0l,
    float* __restrict__ C, int Mdense, int K, int Ncols)
{
    extern __shared__ char dsm[];
    int Mloc = Mdense;
    int bm = blockIdx.x*128; if (bm >= Mloc) return;
    int bn = blockIdx.y*128;
    unsigned sb = su32(dsm);
    int tid = threadIdx.x;
    int aslot = tid&7, arow0 = tid>>3;
    int w = tid>>5, lane = tid&31;
    int wm = (w>>2)*64, wn = (w&3)*32;
    float acc[4][4][4];
    #pragma unroll
    for (int i=0;i<4;i++)
        #pragma unroll
        for (int j=0;j<4;j++)
            #pragma unroll
            for (int q=0;q<4;q++) acc[i][j][q] = 0.f;

    int total = K>>6;
    auto load = [&](int kt){
        unsigned base = sb + (unsigned)(kt%3)*STAGE_BF;
        int ke = kt*64 + aslot*8;
        #pragma unroll
        for (int j=0;j<4;j++){
            int r = arow0 + 32*j;
            unsigned sw = swz((unsigned)(r*128 + aslot*16));
            int ar = bm + r;
            cp16(base+sw,        Ah + (ll)ar*K + ke);
            cp16(base+16384u+sw, Al + (ll)ar*K + ke);
            int br = bn + r;
            cp16(base+32768u+sw, B0h + (ll)br*K + ke);
            cp16(base+49152u+sw, B0l + (ll)br*K + ke);
        }
        asm volatile("cp.async.commit_group;":::"memory");
    };
    if (0 < total) load(0);
    if (1 < total) load(1);
    for (int c = 0; c < total; ++c){
        if (c+1 < total) asm volatile("cp.async.wait_group 1;":::"memory");
        else             asm volatile("cp.async.wait_group 0;":::"memory");
        __syncthreads();

        unsigned base = sb + (unsigned)(c%3)*STAGE_BF;
        int lrow8 = ((lane>>3)&1)*8 + (lane&7);
        #pragma unroll
        for (int ks=0; ks<4; ks++){
            int kb = ks*32 + (lane>>4)*16;
            unsigned BH[2][4], BL[2][4];
            #pragma unroll
            for (int t=0;t<2;t++){
                unsigned sw = swz((unsigned)((wn + t*16 + lrow8)*128 + kb));
                ldsm4(BH[t], base + 32768u + sw);
                ldsm4(BL[t], base + 49152u + sw);
            }
            #pragma unroll
            for (int tm=0;tm<4;tm++){
                unsigned ah[4], al[4];
                unsigned asw = swz((unsigned)((wm + tm*16 + lrow8)*128 + kb));
                ldsm4(ah, base + asw);
                ldsm4(al, base + 16384u + asw);
                #pragma unroll
                for (int t=0;t<2;t++){
                    int j0=2*t, j1=2*t+1;
                    mma_bf(acc[tm][j0], ah, BH[t][0], BH[t][2]);
                    mma_bf(acc[tm][j0], ah, BL[t][0], BL[t][2]);
                    mma_bf(acc[tm][j0], al, BH[t][0], BH[t][2]);
                    mma_bf(acc[tm][j1], ah, BH[t][1], BH[t][3]);
                    mma_bf(acc[tm][j1], ah, BL[t][1], BL[t][3]);
                    mma_bf(acc[tm][j1], al, BH[t][1], BH[t][3]);
                }
            }
        }
        if (c+2 < total) load(c+2);
    }
    #pragma unroll
    for (int tm=0;tm<4;tm++){
        int r = bm + wm + tm*16 + (lane>>2);
        #pragma unroll
        for (int j=0;j<4;j++){
            float* cc = acc[tm][j];
            int col = bn + wn + j*8 + (lane&3)*2;
            *(float2*)(C + (ll)r*Ncols + col) = make_float2(cc[0],cc[1]);
            *(float2*)(C + (ll)(r+8)*Ncols + col) = make_float2(cc[2],cc[3]);
        }
    }
}

// ---------- fp16 1-pass GEMM, 3-stage pipeline, 1 sync/iter, flattened grouped grid ----------
template<int DUAL, int GROUPED>
__global__ __launch_bounds__(256, 2) void mm_f16(
    const __half* __restrict__ Ah,
    const __half* __restrict__ B0, const __half* __restrict__ B1,
    float* __restrict__ C, __half* __restrict__ TH,
    int Mdense, int K, int Ncols,
    const int* __restrict__ d_off, const int* __restrict__ pairtok, ll strideB)
{
    extern __shared__ char dsm[];
    int rowBase = 0, Mloc = Mdense, bm;
    const __half *b0 = B0, *b1 = B1;
    if (GROUPED){
        int idx = blockIdx.x, e = 0;
        int base0 = 0, m = 0;
        #pragma unroll 1
        for (; e < NEXP; e++){
            base0 = d_off[e]; m = d_off[e+1]-base0;
            int nt = (m+127)>>7;
            if (idx < nt) break;
            idx -= nt;
        }
        if (e == NEXP) return;
        rowBase = base0; Mloc = m; bm = idx*128;
        b0 += (ll)e*strideB;
        if (DUAL) b1 += (ll)e*strideB;
    } else {
        bm = blockIdx.x*128;
        if (bm >= Mloc) return;
    }
    int bn = blockIdx.y*(DUAL?64:128);

    unsigned sb = su32(dsm);
    int tid = threadIdx.x;
    int aslot = tid&7, arow0 = tid>>3;
    int ga[4];
    #pragma unroll
    for (int j=0;j<4;j++){
        int lr = bm + arow0 + 32*j; if (lr > Mloc-1) lr = Mloc-1;
        ga[j] = (GROUPED && DUAL) ? pairtok[rowBase+lr] : (rowBase+lr);
    }
    int w = tid>>5, lane = tid&31;
    int wm = DUAL ? (w>>1)*32 : (w>>2)*64;
    int wn = (DUAL ? (w&1) : (w&3))*32;
    constexpr int MT = DUAL ? 2 : 4;
    constexpr int NB = DUAL ? 4 : 2;

    float acc[4][4][4];   // dual: [0..1]=gate, [2..3]=up
    #pragma unroll
    for (int i=0;i<4;i++)
        #pragma unroll
        for (int j=0;j<4;j++)
            #pragma unroll
            for (int q=0;q<4;q++) acc[i][j][q] = 0.f;

    int total = K>>6;
    auto load = [&](int kt){
        unsigned base = sb + (unsigned)(kt%3)*STAGE_HF;
        int ke = kt*64 + aslot*8;
        #pragma unroll
        for (int j=0;j<4;j++){
            int r = arow0 + 32*j;
            unsigned sw = swz((unsigned)(r*128 + aslot*16));
            cp16(base+sw, Ah + (ll)ga[j]*K + ke);
            const __half* bp; int br;
            if (DUAL && r >= 64){ bp = b1; br = bn + r - 64; }
            else                { bp = b0; br = bn + r; }
            cp16(base+16384u+sw, bp + (ll)br*K + ke);
        }
        asm volatile("cp.async.commit_group;":::"memory");
    };
    if (0 < total) load(0);
    if (1 < total) load(1);
    for (int c = 0; c < total; ++c){
        if (c+1 < total) asm volatile("cp.async.wait_group 1;":::"memory");
        else             asm volatile("cp.async.wait_group 0;":::"memory");
        __syncthreads();

        unsigned base = sb + (unsigned)(c%3)*STAGE_HF;
        int lrow8 = ((lane>>3)&1)*8 + (lane&7);
        #pragma unroll
        for (int ks=0; ks<4; ks++){
            int kb = ks*32 + (lane>>4)*16;
            unsigned BH[NB][4];
            #pragma unroll
            for (int t=0;t<NB;t++){
                int nb = (DUAL && t>=2) ? (64 + wn + (t-2)*16) : (wn + t*16);
                ldsm4(BH[t], base + 16384u + swz((unsigned)((nb + lrow8)*128 + kb)));
            }
            #pragma unroll
            for (int tm=0;tm<MT;tm++){
                unsigned ah[4];
                unsigned asw = swz((unsigned)((wm + tm*16 + lrow8)*128 + kb));
                ldsm4(ah, base + asw);
                #pragma unroll
                for (int t=0;t<2;t++){
                    int j0=2*t, j1=2*t+1;
                    mma_hf(acc[tm][j0], ah, BH[t][0], BH[t][2]);
                    mma_hf(acc[tm][j1], ah, BH[t][1], BH[t][3]);
                    if (DUAL){
                        mma_hf(acc[2+tm][j0], ah, BH[2+t][0], BH[2+t][2]);
                        mma_hf(acc[2+tm][j1], ah, BH[2+t][1], BH[2+t][3]);
                    }
                }
            }
        }
        if (c+2 < total) load(c+2);
    }

    if (!DUAL){
        #pragma unroll
        for (int tm=0;tm<4;tm++){
            int r = bm + wm + tm*16 + (lane>>2);
            #pragma unroll
            for (int j=0;j<4;j++){
                float* cc = acc[tm][j];
                int col = bn + wn + j*8 + (lane&3)*2;
                if (r < Mloc)
                    *(float2*)(C + (ll)(rowBase+r)*Ncols + col) = make_float2(cc[0],cc[1]);
                if (r+8 < Mloc)
                    *(float2*)(C + (ll)(rowBase+r+8)*Ncols + col) = make_float2(cc[2],cc[3]);
            }
        }
    } else {
        #pragma unroll
        for (int tm=0;tm<2;tm++){
            int r = bm + wm + tm*16 + (lane>>2);
            #pragma unroll
            for (int j=0;j<4;j++){
                float* gg = acc[tm][j];
                float* uu = acc[2+tm][j];
                float v0 = gg[0]*uu[0]/(1.f+__expf(-gg[0]));
                float v1 = gg[1]*uu[1]/(1.f+__expf(-gg[1]));
                float v2 = gg[2]*uu[2]/(1.f+__expf(-gg[2]));
                float v3 = gg[3]*uu[3]/(1.f+__expf(-gg[3]));
                int col = bn + wn + j*8 + (lane&3)*2;
                __half2 h0, h1;
                h0.x = __float2half_rn(v0); h0.y = __float2half_rn(v1);
                h1.x = __float2half_rn(v2); h1.y = __float2half_rn(v3);
                if (r < Mloc)
                    *(__half2*)(TH + (ll)(rowBase+r)*Ncols + col) = h0;
                if (r+8 < Mloc)
                    *(__half2*)(TH + (ll)(rowBase+r+8)*Ncols + col) = h1;
            }
        }
    }
}

__global__ void combine_rows(const float* __restrict__ enorm, const float* __restrict__ outnorm){
    int t = blockIdx.x, tid = threadIdx.x;
    int s0=g_slotof[2*t], s1=g_slotof[2*t+1], e0=g_topidx[2*t], e1=g_topidx[2*t+1];
    float gg0=g_topgate[2*t], gg1=g_topgate[2*t+1];
    float4 a = ((const float4*)(g_Oe+(ll)s0*DMODEL))[tid];
    float4 b = ((const float4*)(g_Oe+(ll)s1*DMODEL))[tid];
    float ssa=a.x*a.x+a.y*a.y+a.z*a.z+a.w*a.w, ssb=b.x*b.x+b.y*b.y+b.z*b.z+b.w*b.w;
    __shared__ float rA[8],rB[8],rC[8];
    for (int o=16;o;o>>=1){ ssa+=__shfl_xor_sync(~0u,ssa,o); ssb+=__shfl_xor_sync(~0u,ssb,o); }
    if ((tid&31)==0){ rA[tid>>5]=ssa; rB[tid>>5]=ssb; }
    __syncthreads();
    float ta=rA[0]+rA[1]+rA[2]+rA[3]+rA[4]+rA[5]+rA[6]+rA[7];
    float tb=rB[0]+rB[1]+rB[2]+rB[3]+rB[4]+rB[5]+rB[6]+rB[7];
    float r0=rsqrtf(ta*(1.f/DMODEL)+EPSF)*gg0, r1=rsqrtf(tb*(1.f/DMODEL)+EPSF)*gg1;
    float4 w0=((const float4*)(enorm+(ll)e0*DMODEL))[tid];
    float4 w1=((const float4*)(enorm+(ll)e1*DMODEL))[tid];
    float4 c = make_float4(a.x*r0*w0.x+b.x*r1*w1.x, a.y*r0*w0.y+b.y*r1*w1.y,
                           a.z*r0*w0.z+b.z*r1*w1.z, a.w*r0*w0.w+b.w*r1*w1.w);
    float ssc=c.x*c.x+c.y*c.y+c.z*c.z+c.w*c.w;
    for (int o=16;o;o>>=1) ssc+=__shfl_xor_sync(~0u,ssc,o);
    if ((tid&31)==0) rC[tid>>5]=ssc;
    __syncthreads();
    float tc=rC[0]+rC[1]+rC[2]+rC[3]+rC[4]+rC[5]+rC[6]+rC[7];
    float rc=rsqrtf(tc*(1.f/DMODEL)+EPSF);
    float4 wo=((const float4*)outnorm)[tid];
    float4 o4=make_float4(c.x*rc*wo.x, c.y*rc*wo.y, c.z*rc*wo.z, c.w*rc*wo.w);
    __half2 p0,p1;
    p0.x=__float2half_rn(o4.x); p0.y=__float2half_rn(o4.y);
    p1.x=__float2half_rn(o4.z); p1.y=__float2half_rn(o4.w);
    __half2* ph=(__half2*)(g_yHf+(ll)t*DMODEL);
    ph[2*tid]=p0; ph[2*tid+1]=p1;
}

extern "C" void kernel_launch(void* const* d_in, const int* in_sizes, int n_in,
                              void* d_out, int out_size)
{
    const float* s          = (const float*)d_in[0];
    const float* W_in       = (const float*)d_in[1];
    const float* in_norm_w  = (const float*)d_in[2];
    const float* Wr         = (const float*)d_in[3];
    const float* expert_bias= (const float*)d_in[4];
    const float* Wg         = (const float*)d_in[5];
    const float* Wu         = (const float*)d_in[6];
    const float* Wd         = (const float*)d_in[7];
    const float* enorm_w    = (const float*)d_in[8];
    const float* out_norm_w = (const float*)d_in[9];
    const float* W_out      = (const float*)d_in[10];
    float* out = (float*)d_out;

    cudaFuncSetAttribute(mm_bf, cudaFuncAttributeMaxDynamicSharedMemorySize, SMEM_BF);
    cudaFuncSetAttribute(mm_f16<1,1>, cudaFuncAttributeMaxDynamicSharedMemorySize, SMEM_HF);
    cudaFuncSetAttribute(mm_f16<0,1>, cudaFuncAttributeMaxDynamicSharedMemorySize, SMEM_HF);
    cudaFuncSetAttribute(mm_f16<0,0>, cudaFuncAttributeMaxDynamicSharedMemorySize, SMEM_HF);

    void* p;
    #define SYM(v,T,sname) cudaGetSymbolAddress(&p,sname); T* v=(T*)p;
    SYM(h_ptr,float,g_h) SYM(Oe_ptr,float,g_Oe)
    SYM(sH,bf,g_sH) SYM(sL,bf,g_sL)
    SYM(WinH,bf,g_WinH) SYM(WinL,bf,g_WinL)
    SYM(hHf,__half,g_hHf) SYM(yHf,__half,g_yHf)
    SYM(THf,__half,g_THf)
    SYM(WgF,__half,g_WgF) SYM(WuF,__half,g_WuF) SYM(WdF,__half,g_WdF) SYM(WoF,__half,g_WoF)
    SYM(off_ptr,int,g_off) SYM(ptok,int,g_pairtok)
    #undef SYM

    init_counts<<<1,32>>>();
    int nE = NEXP*DFF*DMODEL/4;
    convert_misc<<<dim3(N_TOK*DMODEL/4/256, 3), 256>>>(s, sH, sL, W_in, WinH, WinL, W_out, WoF);
    convert_f16_3<<<dim3((nE+255)/256, 3), 256>>>(Wg, WgF, Wu, WuF, Wd, WdF, nE);

    // h_pre = s @ W_in^T  (bf16 3-pass; protects router)
    mm_bf<<<dim3(N_TOK/128, DMODEL/128), 256, SMEM_BF>>>(
        sH, sL, WinH, WinL, h_ptr, N_TOK, DMODEL, DMODEL);
    // fused rmsnorm + router (h fp32 stays in registers)
    rmsnorm_router<<<N_TOK,256>>>(h_ptr, in_norm_w, hHf, Wr, expert_bias);
    scan_offsets<<<1,32>>>();
    scatter_pairs<<<N_TOK/256,256>>>();

    // T = silu(h Wg^T) * (h Wu^T)  (fp16 1-pass, flattened grouped grid)
    mm_f16<1,1><<<dim3(NPAIR/128 + NEXP, DFF/64), 256, SMEM_HF>>>(
        hHf, WgF, WuF, nullptr, THf,
        0, DMODEL, DFF, off_ptr, ptok, (ll)DFF*DMODEL);

    // Oe = T @ Wd^T  (fp16 1-pass, flattened grouped grid)
    mm_f16<0,1><<<dim3(NPAIR/128 + NEXP, DMODEL/128), 256, SMEM_HF>>>(
        THf, WdF, nullptr, Oe_ptr, nullptr,
        0, DFF, DMODEL, off_ptr, nullptr, (ll)DMODEL*DFF);

    combine_rows<<<N_TOK,256>>>(enorm_w, out_norm_w);

    // out = y @ W_out^T  (fp16 1-pass, dense)
    mm_f16<0,0><<<dim3(N_TOK/128, DMODEL/128), 256, SMEM_HF>>>(
        yHf, WoF, nullptr, out, nullptr,
        N_TOK, DMODEL, DMODEL, nullptr, nullptr, 0);
}

// round 15
// speedup vs baseline: 1.1841x; 1.0218x over previous
#include <cuda_runtime.h>
#include <cuda_bf16.h>
#include <cuda_fp16.h>

#define N_TOK 8192
#define DMODEL 1024
#define DFF 4096
#define NEXP 8
#define NPAIR (N_TOK * 2)
#define EPSF 1.1920928955078125e-07f
#define STAGE_B2 49152u
#define SMEM_B2 (2 * 49152)
#define STAGE_HF 32768u
#define SMEM_HF (3 * 32768)
typedef __nv_bfloat16 bf;
typedef __nv_bfloat162 bf2;
typedef long long ll;

__device__ float g_h[(size_t)N_TOK * DMODEL];
__device__ float g_Oe[(size_t)NPAIR * DMODEL];
__device__ bf g_sH[(size_t)N_TOK*DMODEL], g_sL[(size_t)N_TOK*DMODEL];
__device__ bf g_WinH[(size_t)DMODEL*DMODEL], g_WinL[(size_t)DMODEL*DMODEL];
__device__ __half g_hHf[(size_t)N_TOK*DMODEL];
__device__ __half g_yHf[(size_t)N_TOK*DMODEL];
__device__ __half g_THf[(size_t)NPAIR*DFF];
__device__ __half g_WgF[(size_t)NEXP*DFF*DMODEL];
__device__ __half g_WuF[(size_t)NEXP*DFF*DMODEL];
__device__ __half g_WdF[(size_t)NEXP*DMODEL*DFF];
__device__ __half g_WoF[(size_t)DMODEL*DMODEL];
__device__ int g_cnt[NEXP], g_off[NEXP+1], g_cur[NEXP];
__device__ int g_pairtok[NPAIR], g_slotof[NPAIR], g_topidx[NPAIR];
__device__ float g_topgate[NPAIR];

__device__ __forceinline__ unsigned su32(const void* p){
    unsigned a; asm("{ .reg .u64 t; cvta.to.shared.u64 t, %1; cvt.u32.u64 %0, t; }":"=r"(a):"l"(p)); return a;
}
__device__ __forceinline__ void cp16(unsigned d, const void* s){
    asm volatile("cp.async.cg.shared.global [%0], [%1], 16;"::"r"(d),"l"(s));
}
__device__ __forceinline__ unsigned swz(unsigned off){ return off ^ ((off>>3)&0x70u); }
__device__ __forceinline__ void ldsm4(unsigned* r, unsigned a){
    asm volatile("ldmatrix.sync.aligned.m8n8.x4.shared.b16 {%0,%1,%2,%3}, [%4];"
        :"=r"(r[0]),"=r"(r[1]),"=r"(r[2]),"=r"(r[3]):"r"(a));
}
__device__ __forceinline__ void mma_bf(float* c, const unsigned* a, unsigned b0, unsigned b1){
    asm volatile("mma.sync.aligned.m16n8k16.row.col.f32.bf16.bf16.f32 "
        "{%0,%1,%2,%3},{%4,%5,%6,%7},{%8,%9},{%0,%1,%2,%3};"
        :"+f"(c[0]),"+f"(c[1]),"+f"(c[2]),"+f"(c[3])
        :"r"(a[0]),"r"(a[1]),"r"(a[2]),"r"(a[3]),"r"(b0),"r"(b1));
}
__device__ __forceinline__ void mma_hf(float* c, const unsigned* a, unsigned b0, unsigned b1){
    asm volatile("mma.sync.aligned.m16n8k16.row.col.f32.f16.f16.f32 "
        "{%0,%1,%2,%3},{%4,%5,%6,%7},{%8,%9},{%0,%1,%2,%3};"
        :"+f"(c[0]),"+f"(c[1]),"+f"(c[2]),"+f"(c[3])
        :"r"(a[0]),"r"(a[1]),"r"(a[2]),"r"(a[3]),"r"(b0),"r"(b1));
}
__device__ __forceinline__ void split2(float x, bf& h, bf& l){
    h = __float2bfloat16(x); l = __float2bfloat16(x - __bfloat162float(h));
}

__global__ void init_counts(){ if (threadIdx.x < NEXP) g_cnt[threadIdx.x] = 0; }
__global__ void scan_offsets(){
    if (threadIdx.x == 0){ int s=0; for(int e=0;e<NEXP;e++){ g_off[e]=s; s+=g_cnt[e]; } g_off[NEXP]=s; }
    if (threadIdx.x < NEXP) g_cur[threadIdx.x] = 0;
}
__global__ void scatter_pairs(){
    int t = blockIdx.x*blockDim.x + threadIdx.x; if (t >= N_TOK) return;
    for (int k=0;k<2;k++){
        int e = g_topidx[2*t+k];
        int slot = g_off[e] + atomicAdd(&g_cur[e],1);
        g_pairtok[slot] = t; g_slotof[2*t+k] = slot;
    }
}
__global__ void convert_f16_3(const float* __restrict__ a, __half* __restrict__ oa,
                              const float* __restrict__ b, __half* __restrict__ ob,
                              const float* __restrict__ c, __half* __restrict__ oc, int n4){
    int i = blockIdx.x*blockDim.x + threadIdx.x; if (i >= n4) return;
    const float* x; __half* o;
    if (blockIdx.y == 0){ x=a; o=oa; } else if (blockIdx.y == 1){ x=b; o=ob; } else { x=c; o=oc; }
    float4 v = ((const float4*)x)[i];
    __half2 p0, p1;
    p0.x = __float2half_rn(v.x); p0.y = __float2half_rn(v.y);
    p1.x = __float2half_rn(v.z); p1.y = __float2half_rn(v.w);
    ((__half2*)o)[2*i]=p0; ((__half2*)o)[2*i+1]=p1;
}
__global__ void convert_misc(const float* __restrict__ s, bf* __restrict__ sH, bf* __restrict__ sL,
                             const float* __restrict__ Win, bf* __restrict__ WinH, bf* __restrict__ WinL,
                             const float* __restrict__ Wout, __half* __restrict__ WoF){
    int i = blockIdx.x*blockDim.x + threadIdx.x;
    if (blockIdx.y == 0){
        if (i >= N_TOK*DMODEL/4) return;
        float4 v = ((const float4*)s)[i];
        bf2 p0,p1,q0,q1;
        split2(v.x,p0.x,q0.x); split2(v.y,p0.y,q0.y); split2(v.z,p1.x,q1.x); split2(v.w,p1.y,q1.y);
        ((bf2*)sH)[2*i]=p0; ((bf2*)sH)[2*i+1]=p1; ((bf2*)sL)[2*i]=q0; ((bf2*)sL)[2*i+1]=q1;
    } else if (blockIdx.y == 1){
        if (i >= DMODEL*DMODEL/4) return;
        float4 v = ((const float4*)Win)[i];
        bf2 p0,p1,q0,q1;
        split2(v.x,p0.x,q0.x); split2(v.y,p0.y,q0.y); split2(v.z,p1.x,q1.x); split2(v.w,p1.y,q1.y);
        ((bf2*)WinH)[2*i]=p0; ((bf2*)WinH)[2*i+1]=p1; ((bf2*)WinL)[2*i]=q0; ((bf2*)WinL)[2*i+1]=q1;
    } else {
        if (i >= DMODEL*DMODEL/4) return;
        float4 v = ((const float4*)Wout)[i];
        __half2 p0, p1;
        p0.x = __float2half_rn(v.x); p0.y = __float2half_rn(v.y);
        p1.x = __float2half_rn(v.z); p1.y = __float2half_rn(v.w);
        ((__half2*)WoF)[2*i]=p0; ((__half2*)WoF)[2*i+1]=p1;
    }
}
__global__ void rmsnorm_router(const float* __restrict__ X, const float* __restrict__ w,
                               __half* __restrict__ YH,
                               const float* __restrict__ Wr, const float* __restrict__ bias){
    int row = blockIdx.x, tid = threadIdx.x;
    float4 v = ((const float4*)(X + (ll)row*DMODEL))[tid];
    float ss = v.x*v.x+v.y*v.y+v.z*v.z+v.w*v.w;
    __shared__ float red[8];
    __shared__ float rlog[8][NEXP];
    for (int o=16;o;o>>=1) ss += __shfl_xor_sync(~0u, ss, o);
    if ((tid&31)==0) red[tid>>5]=ss;
    __syncthreads();
    float tot = red[0]+red[1]+red[2]+red[3]+red[4]+red[5]+red[6]+red[7];
    float r = rsqrtf(tot*(1.0f/DMODEL)+EPSF);
    float4 wv = ((const float4*)w)[tid];
    float4 o4 = make_float4(v.x*r*wv.x, v.y*r*wv.y, v.z*r*wv.z, v.w*r*wv.w);
    __half2 p0,p1;
    p0.x = __float2half_rn(o4.x); p0.y = __float2half_rn(o4.y);
    p1.x = __float2half_rn(o4.z); p1.y = __float2half_rn(o4.w);
    __half2* ph=(__half2*)(YH+(ll)row*DMODEL);
    ph[2*tid]=p0; ph[2*tid+1]=p1;
    float part[NEXP];
    #pragma unroll
    for (int e=0;e<NEXP;e++){
        float4 wr = ((const float4*)(Wr + e*DMODEL))[tid];
        part[e] = o4.x*wr.x + o4.y*wr.y + o4.z*wr.z + o4.w*wr.w;
    }
    #pragma unroll
    for (int e=0;e<NEXP;e++)
        for (int o=16;o;o>>=1) part[e] += __shfl_xor_sync(~0u, part[e], o);
    if ((tid&31)==0){
        #pragma unroll
        for (int e=0;e<NEXP;e++) rlog[tid>>5][e] = part[e];
    }
    __syncthreads();
    if (tid == 0){
        float acc[NEXP];
        #pragma unroll
        for (int e=0;e<NEXP;e++){
            float sum = 0.f;
            #pragma unroll
            for (int q=0;q<8;q++) sum += rlog[q][e];
            acc[e] = sum;
        }
        float b0=-1e30f,b1=-1e30f; int i0=0,i1=0;
        #pragma unroll
        for (int e=0;e<NEXP;e++){
            float vv = acc[e]+bias[e];
            if (vv>b0){ b1=b0;i1=i0;b0=vv;i0=e; } else if (vv>b1){ b1=vv;i1=e; }
        }
        float m=fmaxf(acc[i0],acc[i1]);
        float e0=expf(acc[i0]-m), e1=expf(acc[i1]-m), inv=1.f/(e0+e1);
        g_topidx[2*row]=i0; g_topidx[2*row+1]=i1;
        g_topgate[2*row]=e0*inv; g_topgate[2*row+1]=e1*inv;
        atomicAdd(&g_cnt[i0],1); atomicAdd(&g_cnt[i1],1);
    }
}

// ---------- bf16 3-pass dense GEMM, 128x64 tile, 2x48KB stages, 2 CTAs/SM ----------
__global__ __launch_bounds__(256, 2) void mm_bf64(
    const bf* __restrict__ Ah, const bf* __restrict__ Al,
    const bf* __restrict__ B0h, const bf* __restrict__ B0l,
    float* __restrict__ C, int K, int Ncols)
{
    extern __shared__ char dsm[];
    int bm = blockIdx.x*128;
    int bn = blockIdx.y*64;
    unsigned sb = su32(dsm);
    int tid = threadIdx.x;
    int aslot = tid&7, arow0 = tid>>3;
    int w = tid>>5, lane = tid&31;
    int wm = (w>>1)*32, wn = (w&1)*32;
    float acc[2][4][4];
    #pragma unroll
    for (int i=0;i<2;i++)
        #pragma unroll
        for (int j=0;j<4;j++)
            #pragma unroll
            for (int q=0;q<4;q++) acc[i][j][q] = 0.f;

    int total = K>>6;
    auto load = [&](int kt){
        unsigned base = sb + (unsigned)(kt&1)*STAGE_B2;
        int ke = kt*64 + aslot*8;
        #pragma unroll
        for (int j=0;j<4;j++){
            int r = arow0 + 32*j;
            unsigned sw = swz((unsigned)(r*128 + aslot*16));
            int ar = bm + r;
            cp16(base+sw,        Ah + (ll)ar*K + ke);
            cp16(base+16384u+sw, Al + (ll)ar*K + ke);
        }
        #pragma unroll
        for (int j=0;j<2;j++){
            int r = arow0 + 32*j;   // 0..63
            unsigned sw = swz((unsigned)(r*128 + aslot*16));
            int br = bn + r;
            cp16(base+32768u+sw, B0h + (ll)br*K + ke);
            cp16(base+40960u+sw, B0l + (ll)br*K + ke);
        }
        asm volatile("cp.async.commit_group;":::"memory");
    };
    if (0 < total) load(0);
    if (1 < total) load(1);
    for (int c = 0; c < total; ++c){
        if (c+1 < total) asm volatile("cp.async.wait_group 1;":::"memory");
        else             asm volatile("cp.async.wait_group 0;":::"memory");
        __syncthreads();

        unsigned base = sb + (unsigned)(c&1)*STAGE_B2;
        int lrow8 = ((lane>>3)&1)*8 + (lane&7);
        #pragma unroll
        for (int ks=0; ks<4; ks++){
            int kb = ks*32 + (lane>>4)*16;
            unsigned BH[2][4], BL[2][4];
            #pragma unroll
            for (int t=0;t<2;t++){
                unsigned sw = swz((unsigned)((wn + t*16 + lrow8)*128 + kb));
                ldsm4(BH[t], base + 32768u + sw);
                ldsm4(BL[t], base + 40960u + sw);
            }
            #pragma unroll
            for (int tm=0;tm<2;tm++){
                unsigned ah[4], al[4];
                unsigned asw = swz((unsigned)((wm + tm*16 + lrow8)*128 + kb));
                ldsm4(ah, base + asw);
                ldsm4(al, base + 16384u + asw);
                #pragma unroll
                for (int t=0;t<2;t++){
                    int j0=2*t, j1=2*t+1;
                    mma_bf(acc[tm][j0], ah, BH[t][0], BH[t][2]);
                    mma_bf(acc[tm][j0], ah, BL[t][0], BL[t][2]);
                    mma_bf(acc[tm][j0], al, BH[t][0], BH[t][2]);
                    mma_bf(acc[tm][j1], ah, BH[t][1], BH[t][3]);
                    mma_bf(acc[tm][j1], ah, BL[t][1], BL[t][3]);
                    mma_bf(acc[tm][j1], al, BH[t][1], BH[t][3]);
                }
            }
        }
        __syncthreads();
        if (c+2 < total) load(c+2);
    }
    #pragma unroll
    for (int tm=0;tm<2;tm++){
        int r = bm + wm + tm*16 + (lane>>2);
        #pragma unroll
        for (int j=0;j<4;j++){
            float* cc = acc[tm][j];
            int col = bn + wn + j*8 + (lane&3)*2;
            *(float2*)(C + (ll)r*Ncols + col) = make_float2(cc[0],cc[1]);
            *(float2*)(C + (ll)(r+8)*Ncols + col) = make_float2(cc[2],cc[3]);
        }
    }
}

// ---------- fp16 1-pass GEMM, 3-stage pipeline, 1 sync/iter, flattened grouped grid ----------
template<int DUAL, int GROUPED>
__global__ __launch_bounds__(256, 2) void mm_f16(
    const __half* __restrict__ Ah,
    const __half* __restrict__ B0, const __half* __restrict__ B1,
    float* __restrict__ C, __half* __restrict__ TH,
    int Mdense, int K, int Ncols,
    const int* __restrict__ d_off, const int* __restrict__ pairtok, ll strideB)
{
    extern __shared__ char dsm[];
    int rowBase = 0, Mloc = Mdense, bm;
    const __half *b0 = B0, *b1 = B1;
    if (GROUPED){
        int idx = blockIdx.x, e = 0;
        int base0 = 0, m = 0;
        #pragma unroll 1
        for (; e < NEXP; e++){
            base0 = d_off[e]; m = d_off[e+1]-base0;
            int nt = (m+127)>>7;
            if (idx < nt) break;
            idx -= nt;
        }
        if (e == NEXP) return;
        rowBase = base0; Mloc = m; bm = idx*128;
        b0 += (ll)e*strideB;
        if (DUAL) b1 += (ll)e*strideB;
    } else {
        bm = blockIdx.x*128;
        if (bm >= Mloc) return;
    }
    int bn = blockIdx.y*(DUAL?64:128);

    unsigned sb = su32(dsm);
    int tid = threadIdx.x;
    int aslot = tid&7, arow0 = tid>>3;
    int ga[4];
    #pragma unroll
    for (int j=0;j<4;j++){
        int lr = bm + arow0 + 32*j; if (lr > Mloc-1) lr = Mloc-1;
        ga[j] = (GROUPED && DUAL) ? pairtok[rowBase+lr] : (rowBase+lr);
    }
    int w = tid>>5, lane = tid&31;
    int wm = DUAL ? (w>>1)*32 : (w>>2)*64;
    int wn = (DUAL ? (w&1) : (w&3))*32;
    constexpr int MT = DUAL ? 2 : 4;
    constexpr int NB = DUAL ? 4 : 2;

    float acc[4][4][4];
    #pragma unroll
    for (int i=0;i<4;i++)
        #pragma unroll
        for (int j=0;j<4;j++)
            #pragma unroll
            for (int q=0;q<4;q++) acc[i][j][q] = 0.f;

    int total = K>>6;
    auto load = [&](int kt){
        unsigned base = sb + (unsigned)(kt%3)*STAGE_HF;
        int ke = kt*64 + aslot*8;
        #pragma unroll
        for (int j=0;j<4;j++){
            int r = arow0 + 32*j;
            unsigned sw = swz((unsigned)(r*128 + aslot*16));
            cp16(base+sw, Ah + (ll)ga[j]*K + ke);
            const __half* bp; int br;
            if (DUAL && r >= 64){ bp = b1; br = bn + r - 64; }
            else                { bp = b0; br = bn + r; }
            cp16(base+16384u+sw, bp + (ll)br*K + ke);
        }
        asm volatile("cp.async.commit_group;":::"memory");
    };
    if (0 < total) load(0);
    if (1 < total) load(1);
    for (int c = 0; c < total; ++c){
        if (c+1 < total) asm volatile("cp.async.wait_group 1;":::"memory");
        else             asm volatile("cp.async.wait_group 0;":::"memory");
        __syncthreads();

        unsigned base = sb + (unsigned)(c%3)*STAGE_HF;
        int lrow8 = ((lane>>3)&1)*8 + (lane&7);
        #pragma unroll
        for (int ks=0; ks<4; ks++){
            int kb = ks*32 + (lane>>4)*16;
            unsigned BH[NB][4];
            #pragma unroll
            for (int t=0;t<NB;t++){
                int nb = (DUAL && t>=2) ? (64 + wn + (t-2)*16) : (wn + t*16);
                ldsm4(BH[t], base + 16384u + swz((unsigned)((nb + lrow8)*128 + kb)));
            }
            #pragma unroll
            for (int tm=0;tm<MT;tm++){
                unsigned ah[4];
                unsigned asw = swz((unsigned)((wm + tm*16 + lrow8)*128 + kb));
                ldsm4(ah, base + asw);
                #pragma unroll
                for (int t=0;t<2;t++){
                    int j0=2*t, j1=2*t+1;
                    mma_hf(acc[tm][j0], ah, BH[t][0], BH[t][2]);
                    mma_hf(acc[tm][j1], ah, BH[t][1], BH[t][3]);
                    if (DUAL){
                        mma_hf(acc[2+tm][j0], ah, BH[2+t][0], BH[2+t][2]);
                        mma_hf(acc[2+tm][j1], ah, BH[2+t][1], BH[2+t][3]);
                    }
                }
            }
        }
        if (c+2 < total) load(c+2);
    }

    if (!DUAL){
        #pragma unroll
        for (int tm=0;tm<4;tm++){
            int r = bm + wm + tm*16 + (lane>>2);
            #pragma unroll
            for (int j=0;j<4;j++){
                float* cc = acc[tm][j];
                int col = bn + wn + j*8 + (lane&3)*2;
                if (r < Mloc)
                    *(float2*)(C + (ll)(rowBase+r)*Ncols + col) = make_float2(cc[0],cc[1]);
                if (r+8 < Mloc)
                    *(float2*)(C + (ll)(rowBase+r+8)*Ncols + col) = make_float2(cc[2],cc[3]);
            }
        }
    } else {
        #pragma unroll
        for (int tm=0;tm<2;tm++){
            int r = bm + wm + tm*16 + (lane>>2);
            #pragma unroll
            for (int j=0;j<4;j++){
                float* gg = acc[tm][j];
                float* uu = acc[2+tm][j];
                float v0 = gg[0]*uu[0]/(1.f+__expf(-gg[0]));
                float v1 = gg[1]*uu[1]/(1.f+__expf(-gg[1]));
                float v2 = gg[2]*uu[2]/(1.f+__expf(-gg[2]));
                float v3 = gg[3]*uu[3]/(1.f+__expf(-gg[3]));
                int col = bn + wn + j*8 + (lane&3)*2;
                __half2 h0, h1;
                h0.x = __float2half_rn(v0); h0.y = __float2half_rn(v1);
                h1.x = __float2half_rn(v2); h1.y = __float2half_rn(v3);
                if (r < Mloc)
                    *(__half2*)(TH + (ll)(rowBase+r)*Ncols + col) = h0;
                if (r+8 < Mloc)
                    *(__half2*)(TH + (ll)(rowBase+r+8)*Ncols + col) = h1;
            }
        }
    }
}

__global__ void combine_rows(const float* __restrict__ enorm, const float* __restrict__ outnorm){
    int t = blockIdx.x, tid = threadIdx.x;
    int s0=g_slotof[2*t], s1=g_slotof[2*t+1], e0=g_topidx[2*t], e1=g_topidx[2*t+1];
    float gg0=g_topgate[2*t], gg1=g_topgate[2*t+1];
    float4 a = ((const float4*)(g_Oe+(ll)s0*DMODEL))[tid];
    float4 b = ((const float4*)(g_Oe+(ll)s1*DMODEL))[tid];
    float ssa=a.x*a.x+a.y*a.y+a.z*a.z+a.w*a.w, ssb=b.x*b.x+b.y*b.y+b.z*b.z+b.w*b.w;
    __shared__ float rA[8],rB[8],rC[8];
    for (int o=16;o;o>>=1){ ssa+=__shfl_xor_sync(~0u,ssa,o); ssb+=__shfl_xor_sync(~0u,ssb,o); }
    if ((tid&31)==0){ rA[tid>>5]=ssa; rB[tid>>5]=ssb; }
    __syncthreads();
    float ta=rA[0]+rA[1]+rA[2]+rA[3]+rA[4]+rA[5]+rA[6]+rA[7];
    float tb=rB[0]+rB[1]+rB[2]+rB[3]+rB[4]+rB[5]+rB[6]+rB[7];
    float r0=rsqrtf(ta*(1.f/DMODEL)+EPSF)*gg0, r1=rsqrtf(tb*(1.f/DMODEL)+EPSF)*gg1;
    float4 w0=((const float4*)(enorm+(ll)e0*DMODEL))[tid];
    float4 w1=((const float4*)(enorm+(ll)e1*DMODEL))[tid];
    float4 c = make_float4(a.x*r0*w0.x+b.x*r1*w1.x, a.y*r0*w0.y+b.y*r1*w1.y,
                           a.z*r0*w0.z+b.z*r1*w1.z, a.w*r0*w0.w+b.w*r1*w1.w);
    float ssc=c.x*c.x+c.y*c.y+c.z*c.z+c.w*c.w;
    for (int o=16;o;o>>=1) ssc+=__shfl_xor_sync(~0u,ssc,o);
    if ((tid&31)==0) rC[tid>>5]=ssc;
    __syncthreads();
    float tc=rC[0]+rC[1]+rC[2]+rC[3]+rC[4]+rC[5]+rC[6]+rC[7];
    float rc=rsqrtf(tc*(1.f/DMODEL)+EPSF);
    float4 wo=((const float4*)outnorm)[tid];
    float4 o4=make_float4(c.x*rc*wo.x, c.y*rc*wo.y, c.z*rc*wo.z, c.w*rc*wo.w);
    __half2 p0,p1;
    p0.x=__float2half_rn(o4.x); p0.y=__float2half_rn(o4.y);
    p1.x=__float2half_rn(o4.z); p1.y=__float2half_rn(o4.w);
    __half2* ph=(__half2*)(g_yHf+(ll)t*DMODEL);
    ph[2*tid]=p0; ph[2*tid+1]=p1;
}

extern "C" void kernel_launch(void* const* d_in, const int* in_sizes, int n_in,
                              void* d_out, int out_size)
{
    const float* s          = (const float*)d_in[0];
    const float* W_in       = (const float*)d_in[1];
    const float* in_norm_w  = (const float*)d_in[2];
    const float* Wr         = (const float*)d_in[3];
    const float* expert_bias= (const float*)d_in[4];
    const float* Wg         = (const float*)d_in[5];
    const float* Wu         = (const float*)d_in[6];
    const float* Wd         = (const float*)d_in[7];
    const float* enorm_w    = (const float*)d_in[8];
    const float* out_norm_w = (const float*)d_in[9];
    const float* W_out      = (const float*)d_in[10];
    float* out = (float*)d_out;

    static cudaStream_t s2 = nullptr;
    static cudaEvent_t evA = nullptr, evB = nullptr;
    if (!s2){
        cudaStreamCreateWithFlags(&s2, cudaStreamNonBlocking);
        cudaEventCreateWithFlags(&evA, cudaEventDisableTiming);
        cudaEventCreateWithFlags(&evB, cudaEventDisableTiming);
    }

    cudaFuncSetAttribute(mm_bf64, cudaFuncAttributeMaxDynamicSharedMemorySize, SMEM_B2);
    cudaFuncSetAttribute(mm_f16<1,1>, cudaFuncAttributeMaxDynamicSharedMemorySize, SMEM_HF);
    cudaFuncSetAttribute(mm_f16<0,1>, cudaFuncAttributeMaxDynamicSharedMemorySize, SMEM_HF);
    cudaFuncSetAttribute(mm_f16<0,0>, cudaFuncAttributeMaxDynamicSharedMemorySize, SMEM_HF);

    void* p;
    #define SYM(v,T,sname) cudaGetSymbolAddress(&p,sname); T* v=(T*)p;
    SYM(h_ptr,float,g_h) SYM(Oe_ptr,float,g_Oe)
    SYM(sH,bf,g_sH) SYM(sL,bf,g_sL)
    SYM(WinH,bf,g_WinH) SYM(WinL,bf,g_WinL)
    SYM(hHf,__half,g_hHf) SYM(yHf,__half,g_yHf)
    SYM(THf,__half,g_THf)
    SYM(WgF,__half,g_WgF) SYM(WuF,__half,g_WuF) SYM(WdF,__half,g_WdF) SYM(WoF,__half,g_WoF)
    SYM(off_ptr,int,g_off) SYM(ptok,int,g_pairtok)
    #undef SYM

    init_counts<<<1,32>>>();
    int nE = NEXP*DFF*DMODEL/4;

    // fork: expert-weight conversion (DRAM-bound) overlaps in-proj GEMM (tensor-bound)
    cudaEventRecord(evA, 0);
    cudaStreamWaitEvent(s2, evA, 0);
    convert_f16_3<<<dim3((nE+255)/256, 3), 256, 0, s2>>>(Wg, WgF, Wu, WuF, Wd, WdF, nE);
    cudaEventRecord(evB, s2);

    convert_misc<<<dim3(N_TOK*DMODEL/4/256, 3), 256>>>(s, sH, sL, W_in, WinH, WinL, W_out, WoF);

    // h_pre = s @ W_in^T  (bf16 3-pass; protects router)
    mm_bf64<<<dim3(N_TOK/128, DMODEL/64), 256, SMEM_B2>>>(
        sH, sL, WinH, WinL, h_ptr, DMODEL, DMODEL);
    rmsnorm_router<<<N_TOK,256>>>(h_ptr, in_norm_w, hHf, Wr, expert_bias);
    scan_offsets<<<1,32>>>();
    scatter_pairs<<<N_TOK/256,256>>>();

    // join before gateup needs WgF/WuF
    cudaStreamWaitEvent(0, evB, 0);

    // T = silu(h Wg^T) * (h Wu^T)  (fp16 1-pass, flattened grouped grid)
    mm_f16<1,1><<<dim3(NPAIR/128 + NEXP, DFF/64), 256, SMEM_HF>>>(
        hHf, WgF, WuF, nullptr, THf,
        0, DMODEL, DFF, off_ptr, ptok, (ll)DFF*DMODEL);

    // Oe = T @ Wd^T  (fp16 1-pass, flattened grouped grid)
    mm_f16<0,1><<<dim3(NPAIR/128 + NEXP, DMODEL/128), 256, SMEM_HF>>>(
        THf, WdF, nullptr, Oe_ptr, nullptr,
        0, DFF, DMODEL, off_ptr, nullptr, (ll)DMODEL*DFF);

    combine_rows<<<N_TOK,256>>>(enorm_w, out_norm_w);

    // out = y @ W_out^T  (fp16 1-pass, dense)
    mm_f16<0,0><<<dim3(N_TOK/128, DMODEL/128), 256, SMEM_HF>>>(
        yHf, WoF, nullptr, out, nullptr,
        N_TOK, DMODEL, DMODEL, nullptr, nullptr, 0);
}